// round 6
// baseline (speedup 1.0000x reference)
#include <cuda_runtime.h>
#include <cuda_bf16.h>
#include <cstdint>
#include <math.h>

// Problem constants
#define NT    16384      // B*T tokens
#define DIMQ  512
#define HEADS 8
#define DHEAD 64
#define TLEN  4096       // T per batch
#define NB    4          // batch

// ---------------------------------------------------------------------------
// Scratch (device globals — no allocation allowed)
// ---------------------------------------------------------------------------
__device__ float          g_q[NT * DIMQ];
__device__ float          g_k[NT * DIMQ];
__device__ float          g_v[NT * DIMQ];
__device__ __nv_bfloat16  g_xh[NT * DIMQ];
__device__ __nv_bfloat16  g_xl[NT * DIMQ];
__device__ __nv_bfloat16  g_atth[NT * DIMQ];
__device__ __nv_bfloat16  g_attl[NT * DIMQ];
__device__ __nv_bfloat16  g_wh[4 * DIMQ * DIMQ];
__device__ __nv_bfloat16  g_wl[4 * DIMQ * DIMQ];
__device__ float          g_ctx[NB * HEADS * DHEAD * DHEAD];
__device__ float          g_ctxp[NB * HEADS * 8 * DHEAD * DHEAD];
__device__ float          g_ksump[NB * HEADS * 8 * DHEAD];

#define SWZ128(x) ((x) ^ (((x) >> 3) & 0x70))

// ---------------------------------------------------------------------------
// warp-MMA helpers (portable sm_80+ path: LDSM + HMMA + LDGSTS)
// ---------------------------------------------------------------------------
__device__ __forceinline__ uint32_t smem_u32(const void* p) {
    uint32_t a;
    asm("{ .reg .u64 t; cvta.to.shared.u64 t, %1; cvt.u32.u64 %0, t; }"
        : "=r"(a) : "l"(p));
    return a;
}

__device__ __forceinline__ void cp_async16(uint32_t saddr, const void* gaddr) {
    asm volatile("cp.async.cg.shared.global [%0], [%1], 16;"
                 :: "r"(saddr), "l"(gaddr) : "memory");
}
#define CP_COMMIT() asm volatile("cp.async.commit_group;" ::: "memory")
#define CP_WAIT2()  asm volatile("cp.async.wait_group 2;" ::: "memory")

__device__ __forceinline__ void ldsm4(uint32_t* r, uint32_t addr) {
    asm volatile("ldmatrix.sync.aligned.m8n8.x4.shared.b16 {%0,%1,%2,%3}, [%4];"
                 : "=r"(r[0]), "=r"(r[1]), "=r"(r[2]), "=r"(r[3]) : "r"(addr));
}

__device__ __forceinline__ void mma_bf16(float* c, const uint32_t* a,
                                         const uint32_t* b) {
    asm volatile(
        "mma.sync.aligned.m16n8k16.row.col.f32.bf16.bf16.f32 "
        "{%0,%1,%2,%3}, {%4,%5,%6,%7}, {%8,%9}, {%0,%1,%2,%3};"
        : "+f"(c[0]), "+f"(c[1]), "+f"(c[2]), "+f"(c[3])
        : "r"(a[0]), "r"(a[1]), "r"(a[2]), "r"(a[3]), "r"(b[0]), "r"(b[1]));
}

// ---------------------------------------------------------------------------
// fp32 -> bf16 hi/lo split conversion (4 elems/thread)
// ---------------------------------------------------------------------------
__global__ __launch_bounds__(256) void hilo_kernel(
    const float* __restrict__ in, __nv_bfloat16* __restrict__ hi,
    __nv_bfloat16* __restrict__ lo)
{
    size_t i = ((size_t)blockIdx.x * 256 + threadIdx.x) * 4;
    float4 v = *(const float4*)(in + i);
    __nv_bfloat16 h0 = __float2bfloat16(v.x);
    __nv_bfloat16 h1 = __float2bfloat16(v.y);
    __nv_bfloat16 h2 = __float2bfloat16(v.z);
    __nv_bfloat16 h3 = __float2bfloat16(v.w);
    __nv_bfloat16 l0 = __float2bfloat16(v.x - __bfloat162float(h0));
    __nv_bfloat16 l1 = __float2bfloat16(v.y - __bfloat162float(h1));
    __nv_bfloat16 l2 = __float2bfloat16(v.z - __bfloat162float(h2));
    __nv_bfloat16 l3 = __float2bfloat16(v.w - __bfloat162float(h3));
    *(__nv_bfloat162*)(hi + i)     = __nv_bfloat162(h0, h1);
    *(__nv_bfloat162*)(hi + i + 2) = __nv_bfloat162(h2, h3);
    *(__nv_bfloat162*)(lo + i)     = __nv_bfloat162(l0, l1);
    *(__nv_bfloat162*)(lo + i + 2) = __nv_bfloat162(l2, l3);
}

// ---------------------------------------------------------------------------
// bf16x3 GEMM via warp MMA: C[m][n] = sum_k A[m][k]*W[n][k] + bias[n]
// BM=BN=128, BK=64; 8 warps (warp tile 32x64); 3-stage cp.async pipeline.
// grid (DIMQ/128=4, NT/128=128), 256 threads.
// ---------------------------------------------------------------------------
#define GBM 128
#define GBN 128
#define GKS 64
#define GNSL (DIMQ / GKS)            // 8 k-slices
#define TILE_BYTES (128 * 128)       // 16384 per tile (128 rows x 128B)
#define STAGE_BYTES (4 * TILE_BYTES) // Ah, Al, Wh, Wl
#define GEMM_SMEM (3 * STAGE_BYTES)  // 196608

__global__ __launch_bounds__(256) void gemm_bf16x3_kernel(
    const __nv_bfloat16* __restrict__ Ah, const __nv_bfloat16* __restrict__ Al,
    const __nv_bfloat16* __restrict__ Wh, const __nv_bfloat16* __restrict__ Wl,
    const float* __restrict__ bias, float* __restrict__ C)
{
    extern __shared__ __align__(1024) char sm[];
    uint32_t smb = smem_u32(sm);

    const int tid  = threadIdx.x;
    const int wid  = tid >> 5;
    const int lane = tid & 31;
    const int m0 = blockIdx.y * GBM;
    const int n0 = blockIdx.x * GBN;

    const int warp_m = wid & 3;   // 0..3 -> 32 rows each
    const int warp_n = wid >> 2;  // 0..1 -> 64 cols each
    const int mbase = warp_m * 32;
    const int nbase = warp_n * 64;

    const int lr = lane & 7;
    const int g  = lane >> 3;
    // ldmatrix per-thread local offsets (swizzle applied at use site)
    const uint32_t aoff = (uint32_t)(((g & 1) * 8 + lr) * 128 + (g >> 1) * 16);
    const uint32_t boff = (uint32_t)(((g >> 1) * 8 + lr) * 128 + (g & 1) * 16);

    const __nv_bfloat16* srcs[4] = {Ah, Al, Wh, Wl};

    float acc[2][8][4];
#pragma unroll
    for (int i = 0; i < 2; i++)
#pragma unroll
        for (int j = 0; j < 8; j++)
#pragma unroll
            for (int c = 0; c < 4; c++) acc[i][j][c] = 0.0f;

    // ---- stage loader: 4 tiles x 1024 16B-chunks, 16 chunks/thread ----
    auto load_stage = [&](int s) {
        uint32_t stb = smb + (uint32_t)(s % 3) * STAGE_BYTES;
        int k0 = s * GKS;
#pragma unroll
        for (int t = 0; t < 4; t++) {
            const __nv_bfloat16* src = srcs[t];
            int r0 = (t < 2) ? m0 : n0;
            uint32_t tb = stb + (uint32_t)t * TILE_BYTES;
#pragma unroll
            for (int j = 0; j < 4; j++) {
                int il  = tid + j * 256;
                int row = il >> 3;
                int ch  = il & 7;
                uint32_t sa = tb + SWZ128((uint32_t)(row * 128 + ch * 16));
                const void* ga = src + (size_t)(r0 + row) * DIMQ + k0 + ch * 8;
                cp_async16(sa, ga);
            }
        }
    };

    load_stage(0); CP_COMMIT();
    load_stage(1); CP_COMMIT();

    for (int s = 0; s < GNSL; s++) {
        if (s + 2 < GNSL) load_stage(s + 2);
        CP_COMMIT();
        CP_WAIT2();
        __syncthreads();

        uint32_t stb  = smb + (uint32_t)(s % 3) * STAGE_BYTES;
        uint32_t ah_b = stb;
        uint32_t wh_b = stb + 2 * TILE_BYTES;

#pragma unroll
        for (int ks = 0; ks < 4; ks++) {
            uint32_t ksb = (uint32_t)(ks * 32);
            uint32_t aH[2][4], aL[2][4], bH[4][4], bL[4][4];
#pragma unroll
            for (int am = 0; am < 2; am++) {
                uint32_t ad = ah_b + (uint32_t)((mbase + am * 16) * 128)
                            + SWZ128(aoff + ksb);
                ldsm4(aH[am], ad);
                ldsm4(aL[am], ad + TILE_BYTES);
            }
#pragma unroll
            for (int nq = 0; nq < 4; nq++) {
                uint32_t bd = wh_b + (uint32_t)((nbase + nq * 16) * 128)
                            + SWZ128(boff + ksb);
                ldsm4(bH[nq], bd);
                ldsm4(bL[nq], bd + TILE_BYTES);
            }
#pragma unroll
            for (int am = 0; am < 2; am++)
#pragma unroll
                for (int na = 0; na < 8; na++) {
                    const uint32_t* bh = &bH[na >> 1][(na & 1) * 2];
                    const uint32_t* bl = &bL[na >> 1][(na & 1) * 2];
                    mma_bf16(acc[am][na], aH[am], bh);  // Ah*Wh
                    mma_bf16(acc[am][na], aH[am], bl);  // Ah*Wl
                    mma_bf16(acc[am][na], aL[am], bh);  // Al*Wh
                }
        }
        __syncthreads();
    }

    // ---- epilogue: add bias, store fp32 ----
    const int row_in = lane >> 2;        // 0..7
    const int col_in = (lane & 3) * 2;   // 0,2,4,6
#pragma unroll
    for (int am = 0; am < 2; am++) {
        int r = m0 + mbase + am * 16 + row_in;
#pragma unroll
        for (int na = 0; na < 8; na++) {
            int c = n0 + nbase + na * 8 + col_in;
            float2 b = *(const float2*)&bias[c];
            float2 v0 = make_float2(acc[am][na][0] + b.x, acc[am][na][1] + b.y);
            float2 v1 = make_float2(acc[am][na][2] + b.x, acc[am][na][3] + b.y);
            *(float2*)&C[(size_t)r * DIMQ + c]       = v0;
            *(float2*)&C[(size_t)(r + 8) * DIMQ + c] = v1;
        }
    }
}

// ---------------------------------------------------------------------------
// Row softmax over contiguous 64-wide rows (per token, per head). In-place.
// ---------------------------------------------------------------------------
__global__ __launch_bounds__(256) void softmax64_kernel(float* __restrict__ g)
{
    int row  = blockIdx.x * 8 + (threadIdx.x >> 5);
    int lane = threadIdx.x & 31;
    size_t base = (size_t)row * 64 + lane * 2;
    float2 x = *(float2*)&g[base];
    float m = fmaxf(x.x, x.y);
#pragma unroll
    for (int o = 16; o; o >>= 1) m = fmaxf(m, __shfl_xor_sync(0xffffffffu, m, o));
    float e0 = expf(x.x - m);
    float e1 = expf(x.y - m);
    float s = e0 + e1;
#pragma unroll
    for (int o = 16; o; o >>= 1) s += __shfl_xor_sync(0xffffffffu, s, o);
    float inv = 1.0f / s;
    *(float2*)&g[base] = make_float2(e0 * inv, e1 * inv);
}

// ---------------------------------------------------------------------------
// ksum partials
// ---------------------------------------------------------------------------
__global__ void ksum_partial_kernel(const float* __restrict__ K,
                                    float* __restrict__ ksump)
{
    int bh = blockIdx.x;
    int s  = blockIdx.y;
    int b = bh >> 3, h = bh & 7;
    int d = threadIdx.x;
    size_t base = ((size_t)b * TLEN + s * 512) * DIMQ + h * DHEAD + d;
    float acc = 0.0f;
#pragma unroll 8
    for (int t = 0; t < 512; t++) acc += K[base + (size_t)t * DIMQ];
    ksump[((size_t)bh * 8 + s) * DHEAD + d] = acc;
}

// ---------------------------------------------------------------------------
// Context partials
// ---------------------------------------------------------------------------
__global__ __launch_bounds__(256) void ctx_partial_kernel(
    const float* __restrict__ K, const float* __restrict__ V,
    float* __restrict__ ctxp)
{
    int bh = blockIdx.x;
    int s  = blockIdx.y;
    int b = bh >> 3, h = bh & 7;
    const size_t base = ((size_t)b * TLEN + s * 512) * DIMQ + h * DHEAD;

    __shared__ float ks[32][68];
    __shared__ float vs[32][68];

    int tid = threadIdx.x;
    int ty = tid >> 4, tx = tid & 15;
    float acc[4][4];
#pragma unroll
    for (int i = 0; i < 4; i++)
#pragma unroll
        for (int j = 0; j < 4; j++) acc[i][j] = 0.0f;

    int r  = tid >> 3;
    int d4 = (tid & 7) * 4;

    for (int c = 0; c < 16; c++) {
        __syncthreads();
        size_t g = base + (size_t)(c * 32 + r) * DIMQ + d4;
        *(float4*)&ks[r][d4]      = *(const float4*)&K[g];
        *(float4*)&ks[r][d4 + 32] = *(const float4*)&K[g + 32];
        *(float4*)&vs[r][d4]      = *(const float4*)&V[g];
        *(float4*)&vs[r][d4 + 32] = *(const float4*)&V[g + 32];
        __syncthreads();
#pragma unroll
        for (int tt = 0; tt < 32; tt++) {
            float af[4], bf[4];
#pragma unroll
            for (int i = 0; i < 4; i++) af[i] = ks[tt][ty + 16 * i];
#pragma unroll
            for (int j = 0; j < 4; j++) bf[j] = vs[tt][tx + 16 * j];
#pragma unroll
            for (int i = 0; i < 4; i++)
#pragma unroll
                for (int j = 0; j < 4; j++) acc[i][j] += af[i] * bf[j];
        }
    }
    size_t obase = (size_t)(bh * 8 + s) * DHEAD * DHEAD;
#pragma unroll
    for (int i = 0; i < 4; i++)
#pragma unroll
        for (int j = 0; j < 4; j++)
            ctxp[obase + (size_t)(ty + 16 * i) * DHEAD + tx + 16 * j] = acc[i][j];
}

__global__ void ctx_reduce_kernel(const float* __restrict__ ctxp,
                                  float* __restrict__ ctx)
{
    int bh = blockIdx.x;
    for (int idx = threadIdx.x; idx < DHEAD * DHEAD; idx += blockDim.x) {
        float s = 0.0f;
#pragma unroll
        for (int p = 0; p < 8; p++)
            s += ctxp[(size_t)(bh * 8 + p) * DHEAD * DHEAD + idx];
        ctx[(size_t)bh * DHEAD * DHEAD + idx] = s;
    }
}

// ---------------------------------------------------------------------------
// Apply attention + write att directly as bf16 hi/lo for the final GEMM
// ---------------------------------------------------------------------------
__global__ __launch_bounds__(256) void attn_out_kernel(
    const float* __restrict__ Q, const float* __restrict__ ctx,
    const float* __restrict__ ksump,
    __nv_bfloat16* __restrict__ outh, __nv_bfloat16* __restrict__ outl)
{
    int h  = blockIdx.x;
    int t0 = blockIdx.y * 64;
    int b  = t0 / TLEN;
    int bh = b * HEADS + h;

    __shared__ float qst[64][68];   // [d][token]
    __shared__ float cs[64][68];    // [d][e]
    __shared__ float ksum[64];
    __shared__ float dinv[64];

    int tid = threadIdx.x;
    {
        int r  = tid >> 2;
        int d4 = (tid & 3) * 4;
#pragma unroll
        for (int p = 0; p < 4; p++) {
            int d = d4 + p * 16;
            float4 v = *(const float4*)&Q[(size_t)(t0 + r) * DIMQ + h * DHEAD + d];
            qst[d + 0][r] = v.x; qst[d + 1][r] = v.y;
            qst[d + 2][r] = v.z; qst[d + 3][r] = v.w;
        }
        int dr = tid >> 4;
        int e4 = (tid & 15) * 4;
#pragma unroll
        for (int p = 0; p < 4; p++) {
            int d = dr + p * 16;
            *(float4*)&cs[d][e4] =
                *(const float4*)&ctx[((size_t)bh * DHEAD + d) * DHEAD + e4];
        }
    }
    if (tid < 64) {
        float s = 0.0f;
#pragma unroll
        for (int p = 0; p < 8; p++)
            s += ksump[((size_t)bh * 8 + p) * DHEAD + tid];
        ksum[tid] = s;
    }
    __syncthreads();
    if (tid < 64) {
        float s = 0.0f;
#pragma unroll
        for (int d = 0; d < 64; d++) s += qst[d][tid] * ksum[d];
        dinv[tid] = 1.0f / s;
    }
    __syncthreads();

    int ty = tid >> 4, tx = tid & 15;
    float acc[4][4];
#pragma unroll
    for (int i = 0; i < 4; i++)
#pragma unroll
        for (int j = 0; j < 4; j++) acc[i][j] = 0.0f;

#pragma unroll 8
    for (int d = 0; d < 64; d++) {
        float af[4], bf[4];
#pragma unroll
        for (int i = 0; i < 4; i++) af[i] = qst[d][ty + 16 * i];
#pragma unroll
        for (int j = 0; j < 4; j++) bf[j] = cs[d][tx + 16 * j];
#pragma unroll
        for (int i = 0; i < 4; i++)
#pragma unroll
            for (int j = 0; j < 4; j++) acc[i][j] += af[i] * bf[j];
    }

#pragma unroll
    for (int i = 0; i < 4; i++) {
        int r = ty + 16 * i;
        float di = dinv[r];
#pragma unroll
        for (int j = 0; j < 4; j++) {
            int e = tx + 16 * j;
            float val = acc[i][j] * di + qst[e][r];
            size_t idx = (size_t)(t0 + r) * DIMQ + h * DHEAD + e;
            __nv_bfloat16 hi = __float2bfloat16(val);
            outh[idx] = hi;
            outl[idx] = __float2bfloat16(val - __bfloat162float(hi));
        }
    }
}

// ---------------------------------------------------------------------------
extern "C" void kernel_launch(void* const* d_in, const int* in_sizes, int n_in,
                              void* d_out, int out_size)
{
    const float* x  = (const float*)d_in[0];
    const float* Wq = (const float*)d_in[1];
    const float* bq = (const float*)d_in[2];
    const float* Wk = (const float*)d_in[3];
    const float* bk = (const float*)d_in[4];
    const float* Wv = (const float*)d_in[5];
    const float* bv = (const float*)d_in[6];
    const float* Wp = (const float*)d_in[7];
    const float* bp = (const float*)d_in[8];
    float* out = (float*)d_out;

    float *q, *k, *v, *ctx, *ctxp, *ksump;
    __nv_bfloat16 *xh, *xl, *atth, *attl, *wh, *wl;
    cudaGetSymbolAddress((void**)&q, g_q);
    cudaGetSymbolAddress((void**)&k, g_k);
    cudaGetSymbolAddress((void**)&v, g_v);
    cudaGetSymbolAddress((void**)&ctx, g_ctx);
    cudaGetSymbolAddress((void**)&ctxp, g_ctxp);
    cudaGetSymbolAddress((void**)&ksump, g_ksump);
    cudaGetSymbolAddress((void**)&xh, g_xh);
    cudaGetSymbolAddress((void**)&xl, g_xl);
    cudaGetSymbolAddress((void**)&atth, g_atth);
    cudaGetSymbolAddress((void**)&attl, g_attl);
    cudaGetSymbolAddress((void**)&wh, g_wh);
    cudaGetSymbolAddress((void**)&wl, g_wl);

    cudaFuncSetAttribute(gemm_bf16x3_kernel,
                         cudaFuncAttributeMaxDynamicSharedMemorySize, GEMM_SMEM);

    const int WN = DIMQ * DIMQ;  // 262144 per weight matrix

    // hi/lo conversions
    hilo_kernel<<<(NT * DIMQ) / (256 * 4), 256>>>(x, xh, xl);
    hilo_kernel<<<WN / (256 * 4), 256>>>(Wq, wh + 0 * WN, wl + 0 * WN);
    hilo_kernel<<<WN / (256 * 4), 256>>>(Wk, wh + 1 * WN, wl + 1 * WN);
    hilo_kernel<<<WN / (256 * 4), 256>>>(Wv, wh + 2 * WN, wl + 2 * WN);
    hilo_kernel<<<WN / (256 * 4), 256>>>(Wp, wh + 3 * WN, wl + 3 * WN);

    dim3 ggrid(DIMQ / GBN, NT / GBM);  // (4, 128)

    gemm_bf16x3_kernel<<<ggrid, 256, GEMM_SMEM>>>(xh, xl, wh + 0 * WN, wl + 0 * WN, bq, q);
    gemm_bf16x3_kernel<<<ggrid, 256, GEMM_SMEM>>>(xh, xl, wh + 1 * WN, wl + 1 * WN, bk, k);
    gemm_bf16x3_kernel<<<ggrid, 256, GEMM_SMEM>>>(xh, xl, wh + 2 * WN, wl + 2 * WN, bv, v);

    softmax64_kernel<<<(NT * HEADS) / 8, 256>>>(q);
    softmax64_kernel<<<(NT * HEADS) / 8, 256>>>(k);

    ksum_partial_kernel<<<dim3(NB * HEADS, 8), 64>>>(k, ksump);
    ctx_partial_kernel<<<dim3(NB * HEADS, 8), 256>>>(k, v, ctxp);
    ctx_reduce_kernel<<<NB * HEADS, 256>>>(ctxp, ctx);

    attn_out_kernel<<<dim3(HEADS, NT / 64), 256>>>(q, ctx, ksump, atth, attl);

    gemm_bf16x3_kernel<<<ggrid, 256, GEMM_SMEM>>>(atth, attl, wh + 3 * WN, wl + 3 * WN, bp, out);
}

// round 8
// speedup vs baseline: 1.1587x; 1.1587x over previous
#include <cuda_runtime.h>
#include <cuda_bf16.h>
#include <cstdint>
#include <math.h>

// Problem constants
#define NT    16384      // B*T tokens
#define DIMQ  512
#define HEADS 8
#define DHEAD 64
#define TLEN  4096       // T per batch
#define NB    4          // batch

// ---------------------------------------------------------------------------
// Scratch (device globals — no allocation allowed)
// ---------------------------------------------------------------------------
__device__ float          g_q[NT * DIMQ];
__device__ float          g_k[NT * DIMQ];
__device__ float          g_v[NT * DIMQ];
__device__ __nv_bfloat16  g_xh[NT * DIMQ];
__device__ __nv_bfloat16  g_xl[NT * DIMQ];
__device__ __nv_bfloat16  g_atth[NT * DIMQ];
__device__ __nv_bfloat16  g_attl[NT * DIMQ];
__device__ __nv_bfloat16  g_wh[4 * DIMQ * DIMQ];   // Wq,Wk,Wv,Wp rows contiguous
__device__ __nv_bfloat16  g_wl[4 * DIMQ * DIMQ];
__device__ float          g_ctx[NB * HEADS * DHEAD * DHEAD];
__device__ float          g_ctxp[NB * HEADS * 8 * DHEAD * DHEAD];
__device__ float          g_ksump[NB * HEADS * 8 * DHEAD];

#define SWZ128(x) ((x) ^ (((x) >> 3) & 0x70))

// ---------------------------------------------------------------------------
// warp-MMA helpers (portable sm_80+ path: LDSM + HMMA + LDGSTS)
// ---------------------------------------------------------------------------
__device__ __forceinline__ uint32_t smem_u32(const void* p) {
    uint32_t a;
    asm("{ .reg .u64 t; cvta.to.shared.u64 t, %1; cvt.u32.u64 %0, t; }"
        : "=r"(a) : "l"(p));
    return a;
}

__device__ __forceinline__ void cp_async16(uint32_t saddr, const void* gaddr) {
    asm volatile("cp.async.cg.shared.global [%0], [%1], 16;"
                 :: "r"(saddr), "l"(gaddr) : "memory");
}
#define CP_COMMIT() asm volatile("cp.async.commit_group;" ::: "memory")
#define CP_WAIT2()  asm volatile("cp.async.wait_group 2;" ::: "memory")

__device__ __forceinline__ void ldsm4(uint32_t* r, uint32_t addr) {
    asm volatile("ldmatrix.sync.aligned.m8n8.x4.shared.b16 {%0,%1,%2,%3}, [%4];"
                 : "=r"(r[0]), "=r"(r[1]), "=r"(r[2]), "=r"(r[3]) : "r"(addr));
}

__device__ __forceinline__ void mma_bf16(float* c, const uint32_t* a,
                                         const uint32_t* b) {
    asm volatile(
        "mma.sync.aligned.m16n8k16.row.col.f32.bf16.bf16.f32 "
        "{%0,%1,%2,%3}, {%4,%5,%6,%7}, {%8,%9}, {%0,%1,%2,%3};"
        : "+f"(c[0]), "+f"(c[1]), "+f"(c[2]), "+f"(c[3])
        : "r"(a[0]), "r"(a[1]), "r"(a[2]), "r"(a[3]), "r"(b[0]), "r"(b[1]));
}

// ---------------------------------------------------------------------------
// fp32 -> bf16 hi/lo split conversion (4 elems/thread)
// ---------------------------------------------------------------------------
__global__ __launch_bounds__(256) void hilo_kernel(
    const float* __restrict__ in, __nv_bfloat16* __restrict__ hi,
    __nv_bfloat16* __restrict__ lo)
{
    size_t i = ((size_t)blockIdx.x * 256 + threadIdx.x) * 4;
    float4 v = *(const float4*)(in + i);
    __nv_bfloat16 h0 = __float2bfloat16(v.x);
    __nv_bfloat16 h1 = __float2bfloat16(v.y);
    __nv_bfloat16 h2 = __float2bfloat16(v.z);
    __nv_bfloat16 h3 = __float2bfloat16(v.w);
    __nv_bfloat16 l0 = __float2bfloat16(v.x - __bfloat162float(h0));
    __nv_bfloat16 l1 = __float2bfloat16(v.y - __bfloat162float(h1));
    __nv_bfloat16 l2 = __float2bfloat16(v.z - __bfloat162float(h2));
    __nv_bfloat16 l3 = __float2bfloat16(v.w - __bfloat162float(h3));
    *(__nv_bfloat162*)(hi + i)     = __nv_bfloat162(h0, h1);
    *(__nv_bfloat162*)(hi + i + 2) = __nv_bfloat162(h2, h3);
    *(__nv_bfloat162*)(lo + i)     = __nv_bfloat162(l0, l1);
    *(__nv_bfloat162*)(lo + i + 2) = __nv_bfloat162(l2, l3);
}

// All 4 weight matrices in one launch (blockIdx.y selects matrix)
struct WPtrs { const float* w[4]; };
__global__ __launch_bounds__(256) void hilo_w4_kernel(
    WPtrs p, __nv_bfloat16* __restrict__ hi, __nv_bfloat16* __restrict__ lo)
{
    const int WN = DIMQ * DIMQ;
    const float* in = p.w[blockIdx.y];
    size_t off = (size_t)blockIdx.y * WN;
    size_t i = ((size_t)blockIdx.x * 256 + threadIdx.x) * 4;
    float4 v = *(const float4*)(in + i);
    __nv_bfloat16 h0 = __float2bfloat16(v.x);
    __nv_bfloat16 h1 = __float2bfloat16(v.y);
    __nv_bfloat16 h2 = __float2bfloat16(v.z);
    __nv_bfloat16 h3 = __float2bfloat16(v.w);
    __nv_bfloat16 l0 = __float2bfloat16(v.x - __bfloat162float(h0));
    __nv_bfloat16 l1 = __float2bfloat16(v.y - __bfloat162float(h1));
    __nv_bfloat16 l2 = __float2bfloat16(v.z - __bfloat162float(h2));
    __nv_bfloat16 l3 = __float2bfloat16(v.w - __bfloat162float(h3));
    *(__nv_bfloat162*)(hi + off + i)     = __nv_bfloat162(h0, h1);
    *(__nv_bfloat162*)(hi + off + i + 2) = __nv_bfloat162(h2, h3);
    *(__nv_bfloat162*)(lo + off + i)     = __nv_bfloat162(l0, l1);
    *(__nv_bfloat162*)(lo + off + i + 2) = __nv_bfloat162(l2, l3);
}

// ---------------------------------------------------------------------------
// bf16x3 GEMM via warp MMA with fused per-head (64-wide) softmax epilogue.
// C[m][n] = sum_k A[m][k]*W[n][k] + bias[n]; W viewed as [grid.x*128, 512].
// Output/bias selected by n-tile: widx = n0>>9 -> (C0,b0)/(C1,b1)/(C2,b2);
// softmax applied when bit widx of sm_mask is set. Warp tile 32x64 == one head.
// ---------------------------------------------------------------------------
#define GBM 128
#define GBN 128
#define GKS 64
#define GNSL (DIMQ / GKS)            // 8 k-slices
#define TILE_BYTES (128 * 128)       // 16384 per tile (128 rows x 128B)
#define STAGE_BYTES (4 * TILE_BYTES) // Ah, Al, Wh, Wl
#define GEMM_SMEM (3 * STAGE_BYTES)  // 196608

__global__ __launch_bounds__(256) void gemm_bf16x3_kernel(
    const __nv_bfloat16* __restrict__ Ah, const __nv_bfloat16* __restrict__ Al,
    const __nv_bfloat16* __restrict__ Wh, const __nv_bfloat16* __restrict__ Wl,
    const float* __restrict__ b0, const float* __restrict__ b1,
    const float* __restrict__ b2,
    float* __restrict__ C0, float* __restrict__ C1, float* __restrict__ C2,
    int sm_mask)
{
    extern __shared__ __align__(1024) char sm[];
    uint32_t smb = smem_u32(sm);

    const int tid  = threadIdx.x;
    const int wid  = tid >> 5;
    const int lane = tid & 31;
    const int m0 = blockIdx.y * GBM;
    const int n0 = blockIdx.x * GBN;   // global weight-row offset (0..grid.x*128)

    const int widx = n0 >> 9;
    const int col0 = n0 & 511;
    const float* bias = (widx == 0) ? b0 : (widx == 1) ? b1 : b2;
    float* C          = (widx == 0) ? C0 : (widx == 1) ? C1 : C2;
    const bool do_sm  = (sm_mask >> widx) & 1;

    const int warp_m = wid & 3;   // 0..3 -> 32 rows each
    const int warp_n = wid >> 2;  // 0..1 -> 64 cols each (= one head)
    const int mbase = warp_m * 32;
    const int nbase = warp_n * 64;

    const int lr = lane & 7;
    const int g  = lane >> 3;
    const uint32_t aoff = (uint32_t)(((g & 1) * 8 + lr) * 128 + (g >> 1) * 16);
    const uint32_t boff = (uint32_t)(((g >> 1) * 8 + lr) * 128 + (g & 1) * 16);

    const __nv_bfloat16* srcs[4] = {Ah, Al, Wh, Wl};

    float acc[2][8][4];
#pragma unroll
    for (int i = 0; i < 2; i++)
#pragma unroll
        for (int j = 0; j < 8; j++)
#pragma unroll
            for (int c = 0; c < 4; c++) acc[i][j][c] = 0.0f;

    auto load_stage = [&](int s) {
        uint32_t stb = smb + (uint32_t)(s % 3) * STAGE_BYTES;
        int k0 = s * GKS;
#pragma unroll
        for (int t = 0; t < 4; t++) {
            const __nv_bfloat16* src = srcs[t];
            int r0 = (t < 2) ? m0 : n0;
            uint32_t tb = stb + (uint32_t)t * TILE_BYTES;
#pragma unroll
            for (int j = 0; j < 4; j++) {
                int il  = tid + j * 256;
                int row = il >> 3;
                int ch  = il & 7;
                uint32_t sa = tb + SWZ128((uint32_t)(row * 128 + ch * 16));
                const void* ga = src + (size_t)(r0 + row) * DIMQ + k0 + ch * 8;
                cp_async16(sa, ga);
            }
        }
    };

    load_stage(0); CP_COMMIT();
    load_stage(1); CP_COMMIT();

    for (int s = 0; s < GNSL; s++) {
        if (s + 2 < GNSL) load_stage(s + 2);
        CP_COMMIT();
        CP_WAIT2();
        __syncthreads();

        uint32_t stb  = smb + (uint32_t)(s % 3) * STAGE_BYTES;
        uint32_t ah_b = stb;
        uint32_t wh_b = stb + 2 * TILE_BYTES;

#pragma unroll
        for (int ks = 0; ks < 4; ks++) {
            uint32_t ksb = (uint32_t)(ks * 32);
            uint32_t aH[2][4], aL[2][4], bH[4][4], bL[4][4];
#pragma unroll
            for (int am = 0; am < 2; am++) {
                uint32_t ad = ah_b + (uint32_t)((mbase + am * 16) * 128)
                            + SWZ128(aoff + ksb);
                ldsm4(aH[am], ad);
                ldsm4(aL[am], ad + TILE_BYTES);
            }
#pragma unroll
            for (int nq = 0; nq < 4; nq++) {
                uint32_t bd = wh_b + (uint32_t)((nbase + nq * 16) * 128)
                            + SWZ128(boff + ksb);
                ldsm4(bH[nq], bd);
                ldsm4(bL[nq], bd + TILE_BYTES);
            }
#pragma unroll
            for (int am = 0; am < 2; am++)
#pragma unroll
                for (int na = 0; na < 8; na++) {
                    const uint32_t* bh = &bH[na >> 1][(na & 1) * 2];
                    const uint32_t* bl = &bL[na >> 1][(na & 1) * 2];
                    mma_bf16(acc[am][na], aH[am], bh);  // Ah*Wh
                    mma_bf16(acc[am][na], aH[am], bl);  // Ah*Wl
                    mma_bf16(acc[am][na], aL[am], bh);  // Al*Wh
                }
        }
        __syncthreads();
    }

    // ---- epilogue: bias (+ optional per-head softmax), store fp32 ----
    const int row_in = lane >> 2;        // 0..7
    const int col_in = (lane & 3) * 2;   // 0,2,4,6

    float bb[16];
#pragma unroll
    for (int na = 0; na < 8; na++) {
        float2 b = *(const float2*)&bias[col0 + nbase + na * 8 + col_in];
        bb[na * 2] = b.x; bb[na * 2 + 1] = b.y;
    }

#pragma unroll
    for (int am = 0; am < 2; am++) {
#pragma unroll
        for (int sub = 0; sub < 2; sub++) {
            float v[16];
#pragma unroll
            for (int na = 0; na < 8; na++) {
                v[na * 2]     = acc[am][na][sub * 2]     + bb[na * 2];
                v[na * 2 + 1] = acc[am][na][sub * 2 + 1] + bb[na * 2 + 1];
            }
            if (do_sm) {
                // row's 64 cols live in 16 regs x 4 lanes (quad): reduce both
                float m = v[0];
#pragma unroll
                for (int i = 1; i < 16; i++) m = fmaxf(m, v[i]);
                m = fmaxf(m, __shfl_xor_sync(0xffffffffu, m, 1));
                m = fmaxf(m, __shfl_xor_sync(0xffffffffu, m, 2));
                float ssum = 0.0f;
#pragma unroll
                for (int i = 0; i < 16; i++) { v[i] = __expf(v[i] - m); ssum += v[i]; }
                ssum += __shfl_xor_sync(0xffffffffu, ssum, 1);
                ssum += __shfl_xor_sync(0xffffffffu, ssum, 2);
                float inv = 1.0f / ssum;
#pragma unroll
                for (int i = 0; i < 16; i++) v[i] *= inv;
            }
            int r = m0 + mbase + am * 16 + sub * 8 + row_in;
#pragma unroll
            for (int na = 0; na < 8; na++) {
                int c = col0 + nbase + na * 8 + col_in;
                *(float2*)&C[(size_t)r * DIMQ + c] =
                    make_float2(v[na * 2], v[na * 2 + 1]);
            }
        }
    }
}

// ---------------------------------------------------------------------------
// Context partials + fused ksum partials
// ---------------------------------------------------------------------------
__global__ __launch_bounds__(256) void ctx_partial_kernel(
    const float* __restrict__ K, const float* __restrict__ V,
    float* __restrict__ ctxp, float* __restrict__ ksump)
{
    int bh = blockIdx.x;
    int s  = blockIdx.y;
    int b = bh >> 3, h = bh & 7;
    const size_t base = ((size_t)b * TLEN + s * 512) * DIMQ + h * DHEAD;

    __shared__ float ks[32][68];
    __shared__ float vs[32][68];

    int tid = threadIdx.x;
    int ty = tid >> 4, tx = tid & 15;
    float acc[4][4];
#pragma unroll
    for (int i = 0; i < 4; i++)
#pragma unroll
        for (int j = 0; j < 4; j++) acc[i][j] = 0.0f;
    float ksacc = 0.0f;

    int r  = tid >> 3;
    int d4 = (tid & 7) * 4;

    for (int c = 0; c < 16; c++) {
        __syncthreads();
        size_t g = base + (size_t)(c * 32 + r) * DIMQ + d4;
        *(float4*)&ks[r][d4]      = *(const float4*)&K[g];
        *(float4*)&ks[r][d4 + 32] = *(const float4*)&K[g + 32];
        *(float4*)&vs[r][d4]      = *(const float4*)&V[g];
        *(float4*)&vs[r][d4 + 32] = *(const float4*)&V[g + 32];
        __syncthreads();
#pragma unroll
        for (int tt = 0; tt < 32; tt++) {
            float af[4], bf[4];
#pragma unroll
            for (int i = 0; i < 4; i++) af[i] = ks[tt][ty + 16 * i];
#pragma unroll
            for (int j = 0; j < 4; j++) bf[j] = vs[tt][tx + 16 * j];
#pragma unroll
            for (int i = 0; i < 4; i++)
#pragma unroll
                for (int j = 0; j < 4; j++) acc[i][j] += af[i] * bf[j];
        }
        if (tid < 64) {
#pragma unroll
            for (int tt = 0; tt < 32; tt++) ksacc += ks[tt][tid];
        }
    }
    size_t obase = (size_t)(bh * 8 + s) * DHEAD * DHEAD;
#pragma unroll
    for (int i = 0; i < 4; i++)
#pragma unroll
        for (int j = 0; j < 4; j++)
            ctxp[obase + (size_t)(ty + 16 * i) * DHEAD + tx + 16 * j] = acc[i][j];
    if (tid < 64)
        ksump[((size_t)bh * 8 + s) * DHEAD + tid] = ksacc;
}

__global__ void ctx_reduce_kernel(const float* __restrict__ ctxp,
                                  float* __restrict__ ctx)
{
    int bh = blockIdx.x;
    for (int idx = threadIdx.x; idx < DHEAD * DHEAD; idx += blockDim.x) {
        float s = 0.0f;
#pragma unroll
        for (int p = 0; p < 8; p++)
            s += ctxp[(size_t)(bh * 8 + p) * DHEAD * DHEAD + idx];
        ctx[(size_t)bh * DHEAD * DHEAD + idx] = s;
    }
}

// ---------------------------------------------------------------------------
// Apply attention + write att directly as bf16 hi/lo for the final GEMM
// ---------------------------------------------------------------------------
__global__ __launch_bounds__(256) void attn_out_kernel(
    const float* __restrict__ Q, const float* __restrict__ ctx,
    const float* __restrict__ ksump,
    __nv_bfloat16* __restrict__ outh, __nv_bfloat16* __restrict__ outl)
{
    int h  = blockIdx.x;
    int t0 = blockIdx.y * 64;
    int b  = t0 / TLEN;
    int bh = b * HEADS + h;

    __shared__ float qst[64][68];   // [d][token]
    __shared__ float cs[64][68];    // [d][e]
    __shared__ float ksum[64];
    __shared__ float dinv[64];

    int tid = threadIdx.x;
    {
        int r  = tid >> 2;
        int d4 = (tid & 3) * 4;
#pragma unroll
        for (int p = 0; p < 4; p++) {
            int d = d4 + p * 16;
            float4 v = *(const float4*)&Q[(size_t)(t0 + r) * DIMQ + h * DHEAD + d];
            qst[d + 0][r] = v.x; qst[d + 1][r] = v.y;
            qst[d + 2][r] = v.z; qst[d + 3][r] = v.w;
        }
        int dr = tid >> 4;
        int e4 = (tid & 15) * 4;
#pragma unroll
        for (int p = 0; p < 4; p++) {
            int d = dr + p * 16;
            *(float4*)&cs[d][e4] =
                *(const float4*)&ctx[((size_t)bh * DHEAD + d) * DHEAD + e4];
        }
    }
    if (tid < 64) {
        float s = 0.0f;
#pragma unroll
        for (int p = 0; p < 8; p++)
            s += ksump[((size_t)bh * 8 + p) * DHEAD + tid];
        ksum[tid] = s;
    }
    __syncthreads();
    if (tid < 64) {
        float s = 0.0f;
#pragma unroll
        for (int d = 0; d < 64; d++) s += qst[d][tid] * ksum[d];
        dinv[tid] = 1.0f / s;
    }
    __syncthreads();

    int ty = tid >> 4, tx = tid & 15;
    float acc[4][4];
#pragma unroll
    for (int i = 0; i < 4; i++)
#pragma unroll
        for (int j = 0; j < 4; j++) acc[i][j] = 0.0f;

#pragma unroll 8
    for (int d = 0; d < 64; d++) {
        float af[4], bf[4];
#pragma unroll
        for (int i = 0; i < 4; i++) af[i] = qst[d][ty + 16 * i];
#pragma unroll
        for (int j = 0; j < 4; j++) bf[j] = cs[d][tx + 16 * j];
#pragma unroll
        for (int i = 0; i < 4; i++)
#pragma unroll
            for (int j = 0; j < 4; j++) acc[i][j] += af[i] * bf[j];
    }

#pragma unroll
    for (int i = 0; i < 4; i++) {
        int r = ty + 16 * i;
        float di = dinv[r];
#pragma unroll
        for (int j = 0; j < 4; j++) {
            int e = tx + 16 * j;
            float val = acc[i][j] * di + qst[e][r];
            size_t idx = (size_t)(t0 + r) * DIMQ + h * DHEAD + e;
            __nv_bfloat16 hi = __float2bfloat16(val);
            outh[idx] = hi;
            outl[idx] = __float2bfloat16(val - __bfloat162float(hi));
        }
    }
}

// ---------------------------------------------------------------------------
extern "C" void kernel_launch(void* const* d_in, const int* in_sizes, int n_in,
                              void* d_out, int out_size)
{
    const float* x  = (const float*)d_in[0];
    const float* Wq = (const float*)d_in[1];
    const float* bq = (const float*)d_in[2];
    const float* Wk = (const float*)d_in[3];
    const float* bk = (const float*)d_in[4];
    const float* Wv = (const float*)d_in[5];
    const float* bv = (const float*)d_in[6];
    const float* Wp = (const float*)d_in[7];
    const float* bp = (const float*)d_in[8];
    float* out = (float*)d_out;

    float *q, *k, *v, *ctx, *ctxp, *ksump;
    __nv_bfloat16 *xh, *xl, *atth, *attl, *wh, *wl;
    cudaGetSymbolAddress((void**)&q, g_q);
    cudaGetSymbolAddress((void**)&k, g_k);
    cudaGetSymbolAddress((void**)&v, g_v);
    cudaGetSymbolAddress((void**)&ctx, g_ctx);
    cudaGetSymbolAddress((void**)&ctxp, g_ctxp);
    cudaGetSymbolAddress((void**)&ksump, g_ksump);
    cudaGetSymbolAddress((void**)&xh, g_xh);
    cudaGetSymbolAddress((void**)&xl, g_xl);
    cudaGetSymbolAddress((void**)&atth, g_atth);
    cudaGetSymbolAddress((void**)&attl, g_attl);
    cudaGetSymbolAddress((void**)&wh, g_wh);
    cudaGetSymbolAddress((void**)&wl, g_wl);

    cudaFuncSetAttribute(gemm_bf16x3_kernel,
                         cudaFuncAttributeMaxDynamicSharedMemorySize, GEMM_SMEM);

    const int WN = DIMQ * DIMQ;  // 262144 per weight matrix

    // hi/lo conversions: x + all 4 weights (one launch each)
    hilo_kernel<<<(NT * DIMQ) / (256 * 4), 256>>>(x, xh, xl);
    WPtrs wp; wp.w[0] = Wq; wp.w[1] = Wk; wp.w[2] = Wv; wp.w[3] = Wp;
    hilo_w4_kernel<<<dim3(WN / (256 * 4), 4), 256>>>(wp, wh, wl);

    // merged QKV GEMM: W rows [0,1536), softmax fused for q,k (mask 0b011)
    gemm_bf16x3_kernel<<<dim3(3 * DIMQ / GBN, NT / GBM), 256, GEMM_SMEM>>>(
        xh, xl, wh, wl, bq, bk, bv, q, k, v, 0b011);

    ctx_partial_kernel<<<dim3(NB * HEADS, 8), 256>>>(k, v, ctxp, ksump);
    ctx_reduce_kernel<<<NB * HEADS, 256>>>(ctxp, ctx);

    attn_out_kernel<<<dim3(HEADS, NT / 64), 256>>>(q, ctx, ksump, atth, attl);

    // output projection (no softmax)
    gemm_bf16x3_kernel<<<dim3(DIMQ / GBN, NT / GBM), 256, GEMM_SMEM>>>(
        atth, attl, wh + 3 * WN, wl + 3 * WN, bp, bp, bp, out, out, out, 0);
}

// round 9
// speedup vs baseline: 1.1766x; 1.0155x over previous
#include <cuda_runtime.h>
#include <cuda_bf16.h>
#include <cstdint>
#include <math.h>

// Problem constants
#define NT    16384      // B*T tokens
#define DIMQ  512
#define HEADS 8
#define DHEAD 64
#define TLEN  4096       // T per batch
#define NB    4          // batch
#define NSPLIT 32        // T-splits for ctx partials (128 tokens each)

// ---------------------------------------------------------------------------
// Scratch (device globals — no allocation allowed)
// ---------------------------------------------------------------------------
__device__ float          g_q[NT * DIMQ];
__device__ float          g_k[NT * DIMQ];
__device__ float          g_v[NT * DIMQ];
__device__ __nv_bfloat16  g_xh[NT * DIMQ];
__device__ __nv_bfloat16  g_xl[NT * DIMQ];
__device__ __nv_bfloat16  g_atth[NT * DIMQ];
__device__ __nv_bfloat16  g_attl[NT * DIMQ];
__device__ __nv_bfloat16  g_wh[4 * DIMQ * DIMQ];   // Wq,Wk,Wv,Wp rows contiguous
__device__ __nv_bfloat16  g_wl[4 * DIMQ * DIMQ];
__device__ float          g_ctx[NB * HEADS * DHEAD * DHEAD];
__device__ float          g_ctxp[NB * HEADS * NSPLIT * DHEAD * DHEAD];
__device__ float          g_ksump[NB * HEADS * NSPLIT * DHEAD];

#define SWZ128(x) ((x) ^ (((x) >> 3) & 0x70))

// ---------------------------------------------------------------------------
// warp-MMA helpers (portable sm_80+ path: LDSM + HMMA + LDGSTS)
// ---------------------------------------------------------------------------
__device__ __forceinline__ uint32_t smem_u32(const void* p) {
    uint32_t a;
    asm("{ .reg .u64 t; cvta.to.shared.u64 t, %1; cvt.u32.u64 %0, t; }"
        : "=r"(a) : "l"(p));
    return a;
}

__device__ __forceinline__ void cp_async16(uint32_t saddr, const void* gaddr) {
    asm volatile("cp.async.cg.shared.global [%0], [%1], 16;"
                 :: "r"(saddr), "l"(gaddr) : "memory");
}
#define CP_COMMIT() asm volatile("cp.async.commit_group;" ::: "memory")
#define CP_WAIT2()  asm volatile("cp.async.wait_group 2;" ::: "memory")

__device__ __forceinline__ void ldsm4(uint32_t* r, uint32_t addr) {
    asm volatile("ldmatrix.sync.aligned.m8n8.x4.shared.b16 {%0,%1,%2,%3}, [%4];"
                 : "=r"(r[0]), "=r"(r[1]), "=r"(r[2]), "=r"(r[3]) : "r"(addr));
}

__device__ __forceinline__ void mma_bf16(float* c, const uint32_t* a,
                                         const uint32_t* b) {
    asm volatile(
        "mma.sync.aligned.m16n8k16.row.col.f32.bf16.bf16.f32 "
        "{%0,%1,%2,%3}, {%4,%5,%6,%7}, {%8,%9}, {%0,%1,%2,%3};"
        : "+f"(c[0]), "+f"(c[1]), "+f"(c[2]), "+f"(c[3])
        : "r"(a[0]), "r"(a[1]), "r"(a[2]), "r"(a[3]), "r"(b[0]), "r"(b[1]));
}

// ---------------------------------------------------------------------------
// fp32 -> bf16 hi/lo split conversion (4 elems/thread)
// ---------------------------------------------------------------------------
__global__ __launch_bounds__(256) void hilo_kernel(
    const float* __restrict__ in, __nv_bfloat16* __restrict__ hi,
    __nv_bfloat16* __restrict__ lo)
{
    size_t i = ((size_t)blockIdx.x * 256 + threadIdx.x) * 4;
    float4 v = *(const float4*)(in + i);
    __nv_bfloat16 h0 = __float2bfloat16(v.x);
    __nv_bfloat16 h1 = __float2bfloat16(v.y);
    __nv_bfloat16 h2 = __float2bfloat16(v.z);
    __nv_bfloat16 h3 = __float2bfloat16(v.w);
    __nv_bfloat16 l0 = __float2bfloat16(v.x - __bfloat162float(h0));
    __nv_bfloat16 l1 = __float2bfloat16(v.y - __bfloat162float(h1));
    __nv_bfloat16 l2 = __float2bfloat16(v.z - __bfloat162float(h2));
    __nv_bfloat16 l3 = __float2bfloat16(v.w - __bfloat162float(h3));
    *(__nv_bfloat162*)(hi + i)     = __nv_bfloat162(h0, h1);
    *(__nv_bfloat162*)(hi + i + 2) = __nv_bfloat162(h2, h3);
    *(__nv_bfloat162*)(lo + i)     = __nv_bfloat162(l0, l1);
    *(__nv_bfloat162*)(lo + i + 2) = __nv_bfloat162(l2, l3);
}

// All 4 weight matrices in one launch (blockIdx.y selects matrix)
struct WPtrs { const float* w[4]; };
__global__ __launch_bounds__(256) void hilo_w4_kernel(
    WPtrs p, __nv_bfloat16* __restrict__ hi, __nv_bfloat16* __restrict__ lo)
{
    const int WN = DIMQ * DIMQ;
    const float* in = p.w[blockIdx.y];
    size_t off = (size_t)blockIdx.y * WN;
    size_t i = ((size_t)blockIdx.x * 256 + threadIdx.x) * 4;
    float4 v = *(const float4*)(in + i);
    __nv_bfloat16 h0 = __float2bfloat16(v.x);
    __nv_bfloat16 h1 = __float2bfloat16(v.y);
    __nv_bfloat16 h2 = __float2bfloat16(v.z);
    __nv_bfloat16 h3 = __float2bfloat16(v.w);
    __nv_bfloat16 l0 = __float2bfloat16(v.x - __bfloat162float(h0));
    __nv_bfloat16 l1 = __float2bfloat16(v.y - __bfloat162float(h1));
    __nv_bfloat16 l2 = __float2bfloat16(v.z - __bfloat162float(h2));
    __nv_bfloat16 l3 = __float2bfloat16(v.w - __bfloat162float(h3));
    *(__nv_bfloat162*)(hi + off + i)     = __nv_bfloat162(h0, h1);
    *(__nv_bfloat162*)(hi + off + i + 2) = __nv_bfloat162(h2, h3);
    *(__nv_bfloat162*)(lo + off + i)     = __nv_bfloat162(l0, l1);
    *(__nv_bfloat162*)(lo + off + i + 2) = __nv_bfloat162(l2, l3);
}

// ---------------------------------------------------------------------------
// bf16x3 GEMM via warp MMA with fused per-head (64-wide) softmax epilogue.
// ---------------------------------------------------------------------------
#define GBM 128
#define GBN 128
#define GKS 64
#define GNSL (DIMQ / GKS)            // 8 k-slices
#define TILE_BYTES (128 * 128)       // 16384 per tile (128 rows x 128B)
#define STAGE_BYTES (4 * TILE_BYTES) // Ah, Al, Wh, Wl
#define GEMM_SMEM (3 * STAGE_BYTES)  // 196608

__global__ __launch_bounds__(256) void gemm_bf16x3_kernel(
    const __nv_bfloat16* __restrict__ Ah, const __nv_bfloat16* __restrict__ Al,
    const __nv_bfloat16* __restrict__ Wh, const __nv_bfloat16* __restrict__ Wl,
    const float* __restrict__ b0, const float* __restrict__ b1,
    const float* __restrict__ b2,
    float* __restrict__ C0, float* __restrict__ C1, float* __restrict__ C2,
    int sm_mask)
{
    extern __shared__ __align__(1024) char sm[];
    uint32_t smb = smem_u32(sm);

    const int tid  = threadIdx.x;
    const int wid  = tid >> 5;
    const int lane = tid & 31;
    const int m0 = blockIdx.y * GBM;
    const int n0 = blockIdx.x * GBN;   // global weight-row offset

    const int widx = n0 >> 9;
    const int col0 = n0 & 511;
    const float* bias = (widx == 0) ? b0 : (widx == 1) ? b1 : b2;
    float* C          = (widx == 0) ? C0 : (widx == 1) ? C1 : C2;
    const bool do_sm  = (sm_mask >> widx) & 1;

    const int warp_m = wid & 3;   // 0..3 -> 32 rows each
    const int warp_n = wid >> 2;  // 0..1 -> 64 cols each (= one head)
    const int mbase = warp_m * 32;
    const int nbase = warp_n * 64;

    const int lr = lane & 7;
    const int g  = lane >> 3;
    const uint32_t aoff = (uint32_t)(((g & 1) * 8 + lr) * 128 + (g >> 1) * 16);
    const uint32_t boff = (uint32_t)(((g >> 1) * 8 + lr) * 128 + (g & 1) * 16);

    const __nv_bfloat16* srcs[4] = {Ah, Al, Wh, Wl};

    float acc[2][8][4];
#pragma unroll
    for (int i = 0; i < 2; i++)
#pragma unroll
        for (int j = 0; j < 8; j++)
#pragma unroll
            for (int c = 0; c < 4; c++) acc[i][j][c] = 0.0f;

    auto load_stage = [&](int s) {
        uint32_t stb = smb + (uint32_t)(s % 3) * STAGE_BYTES;
        int k0 = s * GKS;
#pragma unroll
        for (int t = 0; t < 4; t++) {
            const __nv_bfloat16* src = srcs[t];
            int r0 = (t < 2) ? m0 : n0;
            uint32_t tb = stb + (uint32_t)t * TILE_BYTES;
#pragma unroll
            for (int j = 0; j < 4; j++) {
                int il  = tid + j * 256;
                int row = il >> 3;
                int ch  = il & 7;
                uint32_t sa = tb + SWZ128((uint32_t)(row * 128 + ch * 16));
                const void* ga = src + (size_t)(r0 + row) * DIMQ + k0 + ch * 8;
                cp_async16(sa, ga);
            }
        }
    };

    load_stage(0); CP_COMMIT();
    load_stage(1); CP_COMMIT();

    for (int s = 0; s < GNSL; s++) {
        if (s + 2 < GNSL) load_stage(s + 2);
        CP_COMMIT();
        CP_WAIT2();
        __syncthreads();

        uint32_t stb  = smb + (uint32_t)(s % 3) * STAGE_BYTES;
        uint32_t ah_b = stb;
        uint32_t wh_b = stb + 2 * TILE_BYTES;

#pragma unroll
        for (int ks = 0; ks < 4; ks++) {
            uint32_t ksb = (uint32_t)(ks * 32);
            uint32_t aH[2][4], aL[2][4], bH[4][4], bL[4][4];
#pragma unroll
            for (int am = 0; am < 2; am++) {
                uint32_t ad = ah_b + (uint32_t)((mbase + am * 16) * 128)
                            + SWZ128(aoff + ksb);
                ldsm4(aH[am], ad);
                ldsm4(aL[am], ad + TILE_BYTES);
            }
#pragma unroll
            for (int nq = 0; nq < 4; nq++) {
                uint32_t bd = wh_b + (uint32_t)((nbase + nq * 16) * 128)
                            + SWZ128(boff + ksb);
                ldsm4(bH[nq], bd);
                ldsm4(bL[nq], bd + TILE_BYTES);
            }
#pragma unroll
            for (int am = 0; am < 2; am++)
#pragma unroll
                for (int na = 0; na < 8; na++) {
                    const uint32_t* bh = &bH[na >> 1][(na & 1) * 2];
                    const uint32_t* bl = &bL[na >> 1][(na & 1) * 2];
                    mma_bf16(acc[am][na], aH[am], bh);  // Ah*Wh
                    mma_bf16(acc[am][na], aH[am], bl);  // Ah*Wl
                    mma_bf16(acc[am][na], aL[am], bh);  // Al*Wh
                }
        }
        __syncthreads();
    }

    // ---- epilogue: bias (+ optional per-head softmax), store fp32 ----
    const int row_in = lane >> 2;        // 0..7
    const int col_in = (lane & 3) * 2;   // 0,2,4,6

    float bb[16];
#pragma unroll
    for (int na = 0; na < 8; na++) {
        float2 b = *(const float2*)&bias[col0 + nbase + na * 8 + col_in];
        bb[na * 2] = b.x; bb[na * 2 + 1] = b.y;
    }

#pragma unroll
    for (int am = 0; am < 2; am++) {
#pragma unroll
        for (int sub = 0; sub < 2; sub++) {
            float v[16];
#pragma unroll
            for (int na = 0; na < 8; na++) {
                v[na * 2]     = acc[am][na][sub * 2]     + bb[na * 2];
                v[na * 2 + 1] = acc[am][na][sub * 2 + 1] + bb[na * 2 + 1];
            }
            if (do_sm) {
                float m = v[0];
#pragma unroll
                for (int i = 1; i < 16; i++) m = fmaxf(m, v[i]);
                m = fmaxf(m, __shfl_xor_sync(0xffffffffu, m, 1));
                m = fmaxf(m, __shfl_xor_sync(0xffffffffu, m, 2));
                float ssum = 0.0f;
#pragma unroll
                for (int i = 0; i < 16; i++) { v[i] = __expf(v[i] - m); ssum += v[i]; }
                ssum += __shfl_xor_sync(0xffffffffu, ssum, 1);
                ssum += __shfl_xor_sync(0xffffffffu, ssum, 2);
                float inv = 1.0f / ssum;
#pragma unroll
                for (int i = 0; i < 16; i++) v[i] *= inv;
            }
            int r = m0 + mbase + am * 16 + sub * 8 + row_in;
#pragma unroll
            for (int na = 0; na < 8; na++) {
                int c = col0 + nbase + na * 8 + col_in;
                *(float2*)&C[(size_t)r * DIMQ + c] =
                    make_float2(v[na * 2], v[na * 2 + 1]);
            }
        }
    }
}

// ---------------------------------------------------------------------------
// Context partials + fused ksum partials.
// grid (NB*HEADS=32, NSPLIT=32): each CTA does a 64x64 outer-product over
// 128 tokens -> high CTA count for occupancy.
// ---------------------------------------------------------------------------
#define SPLIT_T (TLEN / NSPLIT)   // 128 tokens

__global__ __launch_bounds__(256) void ctx_partial_kernel(
    const float* __restrict__ K, const float* __restrict__ V,
    float* __restrict__ ctxp, float* __restrict__ ksump)
{
    int bh = blockIdx.x;
    int s  = blockIdx.y;
    int b = bh >> 3, h = bh & 7;
    const size_t base = ((size_t)b * TLEN + s * SPLIT_T) * DIMQ + h * DHEAD;

    __shared__ float ks[32][68];
    __shared__ float vs[32][68];

    int tid = threadIdx.x;
    int ty = tid >> 4, tx = tid & 15;
    float acc[4][4];
#pragma unroll
    for (int i = 0; i < 4; i++)
#pragma unroll
        for (int j = 0; j < 4; j++) acc[i][j] = 0.0f;
    float ksacc = 0.0f;

    int r  = tid >> 3;
    int d4 = (tid & 7) * 4;

    for (int c = 0; c < SPLIT_T / 32; c++) {
        __syncthreads();
        size_t g = base + (size_t)(c * 32 + r) * DIMQ + d4;
        *(float4*)&ks[r][d4]      = *(const float4*)&K[g];
        *(float4*)&ks[r][d4 + 32] = *(const float4*)&K[g + 32];
        *(float4*)&vs[r][d4]      = *(const float4*)&V[g];
        *(float4*)&vs[r][d4 + 32] = *(const float4*)&V[g + 32];
        __syncthreads();
#pragma unroll
        for (int tt = 0; tt < 32; tt++) {
            float af[4], bf[4];
#pragma unroll
            for (int i = 0; i < 4; i++) af[i] = ks[tt][ty + 16 * i];
#pragma unroll
            for (int j = 0; j < 4; j++) bf[j] = vs[tt][tx + 16 * j];
#pragma unroll
            for (int i = 0; i < 4; i++)
#pragma unroll
                for (int j = 0; j < 4; j++) acc[i][j] += af[i] * bf[j];
        }
        if (tid < 64) {
#pragma unroll
            for (int tt = 0; tt < 32; tt++) ksacc += ks[tt][tid];
        }
    }
    size_t obase = (size_t)(bh * NSPLIT + s) * DHEAD * DHEAD;
#pragma unroll
    for (int i = 0; i < 4; i++)
#pragma unroll
        for (int j = 0; j < 4; j++)
            ctxp[obase + (size_t)(ty + 16 * i) * DHEAD + tx + 16 * j] = acc[i][j];
    if (tid < 64)
        ksump[((size_t)bh * NSPLIT + s) * DHEAD + tid] = ksacc;
}

__global__ void ctx_reduce_kernel(const float* __restrict__ ctxp,
                                  float* __restrict__ ctx)
{
    int bh = blockIdx.x;
    for (int idx = threadIdx.x; idx < DHEAD * DHEAD; idx += blockDim.x) {
        float s = 0.0f;
#pragma unroll
        for (int p = 0; p < NSPLIT; p++)
            s += ctxp[(size_t)(bh * NSPLIT + p) * DHEAD * DHEAD + idx];
        ctx[(size_t)bh * DHEAD * DHEAD + idx] = s;
    }
}

// ---------------------------------------------------------------------------
// Apply attention + write att directly as bf16 hi/lo for the final GEMM
// ---------------------------------------------------------------------------
__global__ __launch_bounds__(256) void attn_out_kernel(
    const float* __restrict__ Q, const float* __restrict__ ctx,
    const float* __restrict__ ksump,
    __nv_bfloat16* __restrict__ outh, __nv_bfloat16* __restrict__ outl)
{
    int h  = blockIdx.x;
    int t0 = blockIdx.y * 64;
    int b  = t0 / TLEN;
    int bh = b * HEADS + h;

    __shared__ float qst[64][68];   // [d][token]
    __shared__ float cs[64][68];    // [d][e]
    __shared__ float ksum[64];
    __shared__ float dinv[64];

    int tid = threadIdx.x;
    {
        int r  = tid >> 2;
        int d4 = (tid & 3) * 4;
#pragma unroll
        for (int p = 0; p < 4; p++) {
            int d = d4 + p * 16;
            float4 v = *(const float4*)&Q[(size_t)(t0 + r) * DIMQ + h * DHEAD + d];
            qst[d + 0][r] = v.x; qst[d + 1][r] = v.y;
            qst[d + 2][r] = v.z; qst[d + 3][r] = v.w;
        }
        int dr = tid >> 4;
        int e4 = (tid & 15) * 4;
#pragma unroll
        for (int p = 0; p < 4; p++) {
            int d = dr + p * 16;
            *(float4*)&cs[d][e4] =
                *(const float4*)&ctx[((size_t)bh * DHEAD + d) * DHEAD + e4];
        }
    }
    if (tid < 64) {
        float s = 0.0f;
#pragma unroll
        for (int p = 0; p < NSPLIT; p++)
            s += ksump[((size_t)bh * NSPLIT + p) * DHEAD + tid];
        ksum[tid] = s;
    }
    __syncthreads();
    if (tid < 64) {
        float s = 0.0f;
#pragma unroll
        for (int d = 0; d < 64; d++) s += qst[d][tid] * ksum[d];
        dinv[tid] = 1.0f / s;
    }
    __syncthreads();

    int ty = tid >> 4, tx = tid & 15;
    float acc[4][4];
#pragma unroll
    for (int i = 0; i < 4; i++)
#pragma unroll
        for (int j = 0; j < 4; j++) acc[i][j] = 0.0f;

#pragma unroll 8
    for (int d = 0; d < 64; d++) {
        float af[4], bf[4];
#pragma unroll
        for (int i = 0; i < 4; i++) af[i] = qst[d][ty + 16 * i];
#pragma unroll
        for (int j = 0; j < 4; j++) bf[j] = cs[d][tx + 16 * j];
#pragma unroll
        for (int i = 0; i < 4; i++)
#pragma unroll
            for (int j = 0; j < 4; j++) acc[i][j] += af[i] * bf[j];
    }

#pragma unroll
    for (int i = 0; i < 4; i++) {
        int r = ty + 16 * i;
        float di = dinv[r];
#pragma unroll
        for (int j = 0; j < 4; j++) {
            int e = tx + 16 * j;
            float val = acc[i][j] * di + qst[e][r];
            size_t idx = (size_t)(t0 + r) * DIMQ + h * DHEAD + e;
            __nv_bfloat16 hi = __float2bfloat16(val);
            outh[idx] = hi;
            outl[idx] = __float2bfloat16(val - __bfloat162float(hi));
        }
    }
}

// ---------------------------------------------------------------------------
extern "C" void kernel_launch(void* const* d_in, const int* in_sizes, int n_in,
                              void* d_out, int out_size)
{
    const float* x  = (const float*)d_in[0];
    const float* Wq = (const float*)d_in[1];
    const float* bq = (const float*)d_in[2];
    const float* Wk = (const float*)d_in[3];
    const float* bk = (const float*)d_in[4];
    const float* Wv = (const float*)d_in[5];
    const float* bv = (const float*)d_in[6];
    const float* Wp = (const float*)d_in[7];
    const float* bp = (const float*)d_in[8];
    float* out = (float*)d_out;

    float *q, *k, *v, *ctx, *ctxp, *ksump;
    __nv_bfloat16 *xh, *xl, *atth, *attl, *wh, *wl;
    cudaGetSymbolAddress((void**)&q, g_q);
    cudaGetSymbolAddress((void**)&k, g_k);
    cudaGetSymbolAddress((void**)&v, g_v);
    cudaGetSymbolAddress((void**)&ctx, g_ctx);
    cudaGetSymbolAddress((void**)&ctxp, g_ctxp);
    cudaGetSymbolAddress((void**)&ksump, g_ksump);
    cudaGetSymbolAddress((void**)&xh, g_xh);
    cudaGetSymbolAddress((void**)&xl, g_xl);
    cudaGetSymbolAddress((void**)&atth, g_atth);
    cudaGetSymbolAddress((void**)&attl, g_attl);
    cudaGetSymbolAddress((void**)&wh, g_wh);
    cudaGetSymbolAddress((void**)&wl, g_wl);

    cudaFuncSetAttribute(gemm_bf16x3_kernel,
                         cudaFuncAttributeMaxDynamicSharedMemorySize, GEMM_SMEM);

    const int WN = DIMQ * DIMQ;  // 262144 per weight matrix

    // hi/lo conversions: x + all 4 weights (one launch each)
    hilo_kernel<<<(NT * DIMQ) / (256 * 4), 256>>>(x, xh, xl);
    WPtrs wp; wp.w[0] = Wq; wp.w[1] = Wk; wp.w[2] = Wv; wp.w[3] = Wp;
    hilo_w4_kernel<<<dim3(WN / (256 * 4), 4), 256>>>(wp, wh, wl);

    // merged QKV GEMM: W rows [0,1536), softmax fused for q,k (mask 0b011)
    gemm_bf16x3_kernel<<<dim3(3 * DIMQ / GBN, NT / GBM), 256, GEMM_SMEM>>>(
        xh, xl, wh, wl, bq, bk, bv, q, k, v, 0b011);

    ctx_partial_kernel<<<dim3(NB * HEADS, NSPLIT), 256>>>(k, v, ctxp, ksump);
    ctx_reduce_kernel<<<NB * HEADS, 256>>>(ctxp, ctx);

    attn_out_kernel<<<dim3(HEADS, NT / 64), 256>>>(q, ctx, ksump, atth, attl);

    // output projection (no softmax)
    gemm_bf16x3_kernel<<<dim3(DIMQ / GBN, NT / GBM), 256, GEMM_SMEM>>>(
        atth, attl, wh + 3 * WN, wl + 3 * WN, bp, bp, bp, out, out, out, 0);
}

// round 12
// speedup vs baseline: 1.2552x; 1.0667x over previous
#include <cuda_runtime.h>
#include <cuda_bf16.h>
#include <cstdint>
#include <math.h>

// Problem constants
#define NT    16384      // B*T tokens
#define DIMQ  512
#define HEADS 8
#define DHEAD 64
#define TLEN  4096       // T per batch
#define NB    4          // batch
#define NSPLIT 16        // T-splits for ctx partials (256 tokens each)

// ---------------------------------------------------------------------------
// Scratch (device globals — no allocation allowed)
// ---------------------------------------------------------------------------
__device__ float          g_q[NT * DIMQ];
__device__ __nv_bfloat16  g_kh[NT * DIMQ];
__device__ __nv_bfloat16  g_kl[NT * DIMQ];
__device__ __nv_bfloat16  g_vh[NT * DIMQ];
__device__ __nv_bfloat16  g_vl[NT * DIMQ];
__device__ __nv_bfloat16  g_xh[NT * DIMQ];
__device__ __nv_bfloat16  g_xl[NT * DIMQ];
__device__ __nv_bfloat16  g_atth[NT * DIMQ];
__device__ __nv_bfloat16  g_attl[NT * DIMQ];
__device__ __nv_bfloat16  g_wh[4 * DIMQ * DIMQ];   // Wq,Wk,Wv,Wp rows contiguous
__device__ __nv_bfloat16  g_wl[4 * DIMQ * DIMQ];
__device__ float          g_ctx[NB * HEADS * DHEAD * DHEAD];
__device__ float          g_ctxp[NB * HEADS * NSPLIT * DHEAD * DHEAD];
__device__ float          g_ksump[NB * HEADS * NSPLIT * DHEAD];

#define SWZ128(x) ((x) ^ (((x) >> 3) & 0x70))

// ---------------------------------------------------------------------------
// warp-MMA helpers
// ---------------------------------------------------------------------------
__device__ __forceinline__ uint32_t smem_u32(const void* p) {
    uint32_t a;
    asm("{ .reg .u64 t; cvta.to.shared.u64 t, %1; cvt.u32.u64 %0, t; }"
        : "=r"(a) : "l"(p));
    return a;
}

__device__ __forceinline__ void cp_async16(uint32_t saddr, const void* gaddr) {
    asm volatile("cp.async.cg.shared.global [%0], [%1], 16;"
                 :: "r"(saddr), "l"(gaddr) : "memory");
}
#define CP_COMMIT() asm volatile("cp.async.commit_group;" ::: "memory")
#define CP_WAIT2()  asm volatile("cp.async.wait_group 2;" ::: "memory")
#define CP_WAIT1()  asm volatile("cp.async.wait_group 1;" ::: "memory")

__device__ __forceinline__ void ldsm4(uint32_t* r, uint32_t addr) {
    asm volatile("ldmatrix.sync.aligned.m8n8.x4.shared.b16 {%0,%1,%2,%3}, [%4];"
                 : "=r"(r[0]), "=r"(r[1]), "=r"(r[2]), "=r"(r[3]) : "r"(addr));
}
__device__ __forceinline__ void ldsm4t(uint32_t* r, uint32_t addr) {
    asm volatile("ldmatrix.sync.aligned.m8n8.x4.trans.shared.b16 {%0,%1,%2,%3}, [%4];"
                 : "=r"(r[0]), "=r"(r[1]), "=r"(r[2]), "=r"(r[3]) : "r"(addr));
}

__device__ __forceinline__ void mma_bf16(float* c, const uint32_t* a,
                                         const uint32_t* b) {
    asm volatile(
        "mma.sync.aligned.m16n8k16.row.col.f32.bf16.bf16.f32 "
        "{%0,%1,%2,%3}, {%4,%5,%6,%7}, {%8,%9}, {%0,%1,%2,%3};"
        : "+f"(c[0]), "+f"(c[1]), "+f"(c[2]), "+f"(c[3])
        : "r"(a[0]), "r"(a[1]), "r"(a[2]), "r"(a[3]), "r"(b[0]), "r"(b[1]));
}

__device__ __forceinline__ float lds_bf16(uint32_t a) {
    uint32_t v;
    asm volatile("ld.shared.u16 %0, [%1];" : "=r"(v) : "r"(a));
    __nv_bfloat16_raw r; r.x = (unsigned short)v;
    return __bfloat162float(__nv_bfloat16(r));
}

// ---------------------------------------------------------------------------
// fp32 -> bf16 hi/lo split conversion (4 elems/thread)
// ---------------------------------------------------------------------------
__global__ __launch_bounds__(256) void hilo_kernel(
    const float* __restrict__ in, __nv_bfloat16* __restrict__ hi,
    __nv_bfloat16* __restrict__ lo)
{
    size_t i = ((size_t)blockIdx.x * 256 + threadIdx.x) * 4;
    float4 v = *(const float4*)(in + i);
    __nv_bfloat16 h0 = __float2bfloat16(v.x);
    __nv_bfloat16 h1 = __float2bfloat16(v.y);
    __nv_bfloat16 h2 = __float2bfloat16(v.z);
    __nv_bfloat16 h3 = __float2bfloat16(v.w);
    __nv_bfloat16 l0 = __float2bfloat16(v.x - __bfloat162float(h0));
    __nv_bfloat16 l1 = __float2bfloat16(v.y - __bfloat162float(h1));
    __nv_bfloat16 l2 = __float2bfloat16(v.z - __bfloat162float(h2));
    __nv_bfloat16 l3 = __float2bfloat16(v.w - __bfloat162float(h3));
    *(__nv_bfloat162*)(hi + i)     = __nv_bfloat162(h0, h1);
    *(__nv_bfloat162*)(hi + i + 2) = __nv_bfloat162(h2, h3);
    *(__nv_bfloat162*)(lo + i)     = __nv_bfloat162(l0, l1);
    *(__nv_bfloat162*)(lo + i + 2) = __nv_bfloat162(l2, l3);
}

struct WPtrs { const float* w[4]; };
__global__ __launch_bounds__(256) void hilo_w4_kernel(
    WPtrs p, __nv_bfloat16* __restrict__ hi, __nv_bfloat16* __restrict__ lo)
{
    const int WN = DIMQ * DIMQ;
    const float* in = p.w[blockIdx.y];
    size_t off = (size_t)blockIdx.y * WN;
    size_t i = ((size_t)blockIdx.x * 256 + threadIdx.x) * 4;
    float4 v = *(const float4*)(in + i);
    __nv_bfloat16 h0 = __float2bfloat16(v.x);
    __nv_bfloat16 h1 = __float2bfloat16(v.y);
    __nv_bfloat16 h2 = __float2bfloat16(v.z);
    __nv_bfloat16 h3 = __float2bfloat16(v.w);
    __nv_bfloat16 l0 = __float2bfloat16(v.x - __bfloat162float(h0));
    __nv_bfloat16 l1 = __float2bfloat16(v.y - __bfloat162float(h1));
    __nv_bfloat16 l2 = __float2bfloat16(v.z - __bfloat162float(h2));
    __nv_bfloat16 l3 = __float2bfloat16(v.w - __bfloat162float(h3));
    *(__nv_bfloat162*)(hi + off + i)     = __nv_bfloat162(h0, h1);
    *(__nv_bfloat162*)(hi + off + i + 2) = __nv_bfloat162(h2, h3);
    *(__nv_bfloat162*)(lo + off + i)     = __nv_bfloat162(l0, l1);
    *(__nv_bfloat162*)(lo + off + i + 2) = __nv_bfloat162(l2, l3);
}

// ---------------------------------------------------------------------------
// bf16x3 GEMM via warp MMA with fused per-head softmax epilogue.
// widx 0: q -> fp32 (+softmax); widx 1: k -> bf16 hi/lo (+softmax);
// widx 2: v -> bf16 hi/lo.
// ---------------------------------------------------------------------------
#define GBM 128
#define GBN 128
#define GKS 64
#define GNSL (DIMQ / GKS)            // 8 k-slices
#define TILE_BYTES (128 * 128)
#define STAGE_BYTES (4 * TILE_BYTES)
#define GEMM_SMEM (3 * STAGE_BYTES)  // 196608

__global__ __launch_bounds__(256) void gemm_bf16x3_kernel(
    const __nv_bfloat16* __restrict__ Ah, const __nv_bfloat16* __restrict__ Al,
    const __nv_bfloat16* __restrict__ Wh, const __nv_bfloat16* __restrict__ Wl,
    const float* __restrict__ b0, const float* __restrict__ b1,
    const float* __restrict__ b2,
    float* __restrict__ Cq,
    __nv_bfloat16* __restrict__ Kh, __nv_bfloat16* __restrict__ Kl,
    __nv_bfloat16* __restrict__ Vh, __nv_bfloat16* __restrict__ Vl,
    int sm_mask)
{
    extern __shared__ __align__(1024) char sm[];
    uint32_t smb = smem_u32(sm);

    const int tid  = threadIdx.x;
    const int wid  = tid >> 5;
    const int lane = tid & 31;
    const int m0 = blockIdx.y * GBM;
    const int n0 = blockIdx.x * GBN;

    const int widx = n0 >> 9;
    const int col0 = n0 & 511;
    const float* bias = (widx == 0) ? b0 : (widx == 1) ? b1 : b2;
    const bool do_sm  = (sm_mask >> widx) & 1;

    const int warp_m = wid & 3;
    const int warp_n = wid >> 2;
    const int mbase = warp_m * 32;
    const int nbase = warp_n * 64;

    const int lr = lane & 7;
    const int g  = lane >> 3;
    const uint32_t aoff = (uint32_t)(((g & 1) * 8 + lr) * 128 + (g >> 1) * 16);
    const uint32_t boff = (uint32_t)(((g >> 1) * 8 + lr) * 128 + (g & 1) * 16);

    const __nv_bfloat16* srcs[4] = {Ah, Al, Wh, Wl};

    float acc[2][8][4];
#pragma unroll
    for (int i = 0; i < 2; i++)
#pragma unroll
        for (int j = 0; j < 8; j++)
#pragma unroll
            for (int c = 0; c < 4; c++) acc[i][j][c] = 0.0f;

    auto load_stage = [&](int s) {
        uint32_t stb = smb + (uint32_t)(s % 3) * STAGE_BYTES;
        int k0 = s * GKS;
#pragma unroll
        for (int t = 0; t < 4; t++) {
            const __nv_bfloat16* src = srcs[t];
            int r0 = (t < 2) ? m0 : n0;
            uint32_t tb = stb + (uint32_t)t * TILE_BYTES;
#pragma unroll
            for (int j = 0; j < 4; j++) {
                int il  = tid + j * 256;
                int row = il >> 3;
                int ch  = il & 7;
                uint32_t sa = tb + SWZ128((uint32_t)(row * 128 + ch * 16));
                const void* ga = src + (size_t)(r0 + row) * DIMQ + k0 + ch * 8;
                cp_async16(sa, ga);
            }
        }
    };

    load_stage(0); CP_COMMIT();
    load_stage(1); CP_COMMIT();

    for (int s = 0; s < GNSL; s++) {
        if (s + 2 < GNSL) load_stage(s + 2);
        CP_COMMIT();
        CP_WAIT2();
        __syncthreads();

        uint32_t stb  = smb + (uint32_t)(s % 3) * STAGE_BYTES;
        uint32_t ah_b = stb;
        uint32_t wh_b = stb + 2 * TILE_BYTES;

#pragma unroll
        for (int ks = 0; ks < 4; ks++) {
            uint32_t ksb = (uint32_t)(ks * 32);
            uint32_t aH[2][4], aL[2][4], bH[4][4], bL[4][4];
#pragma unroll
            for (int am = 0; am < 2; am++) {
                uint32_t ad = ah_b + (uint32_t)((mbase + am * 16) * 128)
                            + SWZ128(aoff + ksb);
                ldsm4(aH[am], ad);
                ldsm4(aL[am], ad + TILE_BYTES);
            }
#pragma unroll
            for (int nq = 0; nq < 4; nq++) {
                uint32_t bd = wh_b + (uint32_t)((nbase + nq * 16) * 128)
                            + SWZ128(boff + ksb);
                ldsm4(bH[nq], bd);
                ldsm4(bL[nq], bd + TILE_BYTES);
            }
#pragma unroll
            for (int am = 0; am < 2; am++)
#pragma unroll
                for (int na = 0; na < 8; na++) {
                    const uint32_t* bh = &bH[na >> 1][(na & 1) * 2];
                    const uint32_t* bl = &bL[na >> 1][(na & 1) * 2];
                    mma_bf16(acc[am][na], aH[am], bh);
                    mma_bf16(acc[am][na], aH[am], bl);
                    mma_bf16(acc[am][na], aL[am], bh);
                }
        }
        __syncthreads();
    }

    // ---- epilogue: bias (+ optional softmax), store fp32 or bf16 hi/lo ----
    const int row_in = lane >> 2;
    const int col_in = (lane & 3) * 2;

    __nv_bfloat16* Oh = (widx == 1) ? Kh : Vh;
    __nv_bfloat16* Ol = (widx == 1) ? Kl : Vl;

    float bb[16];
#pragma unroll
    for (int na = 0; na < 8; na++) {
        float2 b = *(const float2*)&bias[col0 + nbase + na * 8 + col_in];
        bb[na * 2] = b.x; bb[na * 2 + 1] = b.y;
    }

#pragma unroll
    for (int am = 0; am < 2; am++) {
#pragma unroll
        for (int sub = 0; sub < 2; sub++) {
            float v[16];
#pragma unroll
            for (int na = 0; na < 8; na++) {
                v[na * 2]     = acc[am][na][sub * 2]     + bb[na * 2];
                v[na * 2 + 1] = acc[am][na][sub * 2 + 1] + bb[na * 2 + 1];
            }
            if (do_sm) {
                float m = v[0];
#pragma unroll
                for (int i = 1; i < 16; i++) m = fmaxf(m, v[i]);
                m = fmaxf(m, __shfl_xor_sync(0xffffffffu, m, 1));
                m = fmaxf(m, __shfl_xor_sync(0xffffffffu, m, 2));
                float ssum = 0.0f;
#pragma unroll
                for (int i = 0; i < 16; i++) { v[i] = __expf(v[i] - m); ssum += v[i]; }
                ssum += __shfl_xor_sync(0xffffffffu, ssum, 1);
                ssum += __shfl_xor_sync(0xffffffffu, ssum, 2);
                float inv = 1.0f / ssum;
#pragma unroll
                for (int i = 0; i < 16; i++) v[i] *= inv;
            }
            int r = m0 + mbase + am * 16 + sub * 8 + row_in;
            if (widx == 0) {
#pragma unroll
                for (int na = 0; na < 8; na++) {
                    int c = col0 + nbase + na * 8 + col_in;
                    *(float2*)&Cq[(size_t)r * DIMQ + c] =
                        make_float2(v[na * 2], v[na * 2 + 1]);
                }
            } else {
#pragma unroll
                for (int na = 0; na < 8; na++) {
                    int c = col0 + nbase + na * 8 + col_in;
                    __nv_bfloat16 h0 = __float2bfloat16(v[na * 2]);
                    __nv_bfloat16 h1 = __float2bfloat16(v[na * 2 + 1]);
                    __nv_bfloat16 l0 = __float2bfloat16(v[na * 2]     - __bfloat162float(h0));
                    __nv_bfloat16 l1 = __float2bfloat16(v[na * 2 + 1] - __bfloat162float(h1));
                    *(__nv_bfloat162*)&Oh[(size_t)r * DIMQ + c] = __nv_bfloat162(h0, h1);
                    *(__nv_bfloat162*)&Ol[(size_t)r * DIMQ + c] = __nv_bfloat162(l0, l1);
                }
            }
        }
    }
}

// ---------------------------------------------------------------------------
// ctx partials via tensor cores: ctxp[bh][s][d][e] = sum_t k[t][d]*v[t][e]
// over 256 tokens, bf16x3 (kh,kl)x(vh,vl). Also emits ksum partials.
// grid (32, NSPLIT=16), 128 threads (4 warps; warp = 16 d-rows).
// ---------------------------------------------------------------------------
#define CCH 64                         // tokens per chunk
#define CTILE 8192                     // 64 x 128B
#define CSTAGE (4 * CTILE)             // kh,kl,vh,vl
#define CTX_SMEM (2 * CSTAGE)          // 65536

__global__ __launch_bounds__(128) void ctx_mma_kernel(
    const __nv_bfloat16* __restrict__ Kh, const __nv_bfloat16* __restrict__ Kl,
    const __nv_bfloat16* __restrict__ Vh, const __nv_bfloat16* __restrict__ Vl,
    float* __restrict__ ctxp, float* __restrict__ ksump)
{
    extern __shared__ __align__(1024) char sm[];
    uint32_t smb = smem_u32(sm);

    const int bh = blockIdx.x;
    const int s  = blockIdx.y;
    const int b = bh >> 3, h = bh & 7;
    const int tid = threadIdx.x;
    const int wid = tid >> 5, lane = tid & 31;

    const size_t tok0 = (size_t)b * TLEN + s * (TLEN / NSPLIT);
    const __nv_bfloat16* srcs[4] = {Kh, Kl, Vh, Vl};

    // trans-ldmatrix lane addressing
    const int arow = (lane & 7) + 8 * ((lane >> 4) & 1);
    const int acolX = wid * 32 + 16 * ((lane >> 3) & 1);   // d-bytes
    const int brow = (lane & 7) + 8 * ((lane >> 3) & 1);
    const int bcolX = 16 * ((lane >> 4) & 1);              // e-bytes (within n16 blk)

    auto load_chunk = [&](int c, int buf) {
        uint32_t stb = smb + (uint32_t)buf * CSTAGE;
#pragma unroll
        for (int i = 0; i < 16; i++) {
            int idx  = tid + i * 128;
            int tile = idx >> 9;
            int rem  = idx & 511;
            int row  = rem >> 3;
            int ch   = rem & 7;
            uint32_t sa = stb + (uint32_t)tile * CTILE
                        + SWZ128((uint32_t)(row * 128 + ch * 16));
            const void* ga = srcs[tile]
                + (tok0 + c * CCH + row) * DIMQ + h * DHEAD + ch * 8;
            cp_async16(sa, ga);
        }
    };

    float acc[8][4];
#pragma unroll
    for (int j = 0; j < 8; j++)
#pragma unroll
        for (int c = 0; c < 4; c++) acc[j][c] = 0.0f;
    float ksacc = 0.0f;

    load_chunk(0, 0); CP_COMMIT();

    const int NCH = (TLEN / NSPLIT) / CCH;  // 4
    for (int c = 0; c < NCH; c++) {
        if (c + 1 < NCH) load_chunk(c + 1, (c + 1) & 1);
        CP_COMMIT();
        CP_WAIT1();
        __syncthreads();

        uint32_t st = smb + (uint32_t)(c & 1) * CSTAGE;
#pragma unroll
        for (int kk = 0; kk < 4; kk++) {
            int t0 = kk * 16;
            uint32_t aH[4], aL[4], vH[4][4], vL[4][4];
            uint32_t ad = st + SWZ128((uint32_t)((t0 + arow) * 128 + acolX));
            ldsm4t(aH, ad);
            ldsm4t(aL, ad + CTILE);
#pragma unroll
            for (int nb2 = 0; nb2 < 4; nb2++) {
                uint32_t bd = st + 2 * CTILE
                    + SWZ128((uint32_t)((t0 + brow) * 128 + nb2 * 32 + bcolX));
                ldsm4t(vH[nb2], bd);
                ldsm4t(vL[nb2], bd + CTILE);
            }
#pragma unroll
            for (int nb = 0; nb < 8; nb++) {
                const uint32_t* bh_ = &vH[nb >> 1][(nb & 1) * 2];
                const uint32_t* bl_ = &vL[nb >> 1][(nb & 1) * 2];
                mma_bf16(acc[nb], aH, bh_);
                mma_bf16(acc[nb], aH, bl_);
                mma_bf16(acc[nb], aL, bh_);
            }
        }
        if (tid < 64) {
#pragma unroll 8
            for (int t = 0; t < CCH; t++) {
                uint32_t off = SWZ128((uint32_t)(t * 128 + tid * 2));
                ksacc += lds_bf16(st + off) + lds_bf16(st + CTILE + off);
            }
        }
        __syncthreads();
    }

    // write partials
    size_t obase = ((size_t)bh * NSPLIT + s) * (DHEAD * DHEAD);
    int r1 = wid * 16 + (lane >> 2);
    int ec = (lane & 3) * 2;
#pragma unroll
    for (int nb = 0; nb < 8; nb++) {
        int e = nb * 8 + ec;
        *(float2*)&ctxp[obase + (size_t)r1 * DHEAD + e] =
            make_float2(acc[nb][0], acc[nb][1]);
        *(float2*)&ctxp[obase + (size_t)(r1 + 8) * DHEAD + e] =
            make_float2(acc[nb][2], acc[nb][3]);
    }
    if (tid < 64)
        ksump[((size_t)bh * NSPLIT + s) * DHEAD + tid] = ksacc;
}

__global__ void ctx_reduce_kernel(const float* __restrict__ ctxp,
                                  float* __restrict__ ctx)
{
    int bh = blockIdx.x;
    for (int idx = threadIdx.x; idx < DHEAD * DHEAD; idx += blockDim.x) {
        float s = 0.0f;
#pragma unroll
        for (int p = 0; p < NSPLIT; p++)
            s += ctxp[(size_t)(bh * NSPLIT + p) * DHEAD * DHEAD + idx];
        ctx[(size_t)bh * DHEAD * DHEAD + idx] = s;
    }
}

// ---------------------------------------------------------------------------
// Apply attention + write att directly as bf16 hi/lo for the final GEMM
// ---------------------------------------------------------------------------
__global__ __launch_bounds__(256) void attn_out_kernel(
    const float* __restrict__ Q, const float* __restrict__ ctx,
    const float* __restrict__ ksump,
    __nv_bfloat16* __restrict__ outh, __nv_bfloat16* __restrict__ outl)
{
    int h  = blockIdx.x;
    int t0 = blockIdx.y * 64;
    int b  = t0 / TLEN;
    int bh = b * HEADS + h;

    __shared__ float qst[64][68];
    __shared__ float cs[64][68];
    __shared__ float ksum[64];
    __shared__ float dinv[64];

    int tid = threadIdx.x;
    {
        int r  = tid >> 2;
        int d4 = (tid & 3) * 4;
#pragma unroll
        for (int p = 0; p < 4; p++) {
            int d = d4 + p * 16;
            float4 v = *(const float4*)&Q[(size_t)(t0 + r) * DIMQ + h * DHEAD + d];
            qst[d + 0][r] = v.x; qst[d + 1][r] = v.y;
            qst[d + 2][r] = v.z; qst[d + 3][r] = v.w;
        }
        int dr = tid >> 4;
        int e4 = (tid & 15) * 4;
#pragma unroll
        for (int p = 0; p < 4; p++) {
            int d = dr + p * 16;
            *(float4*)&cs[d][e4] =
                *(const float4*)&ctx[((size_t)bh * DHEAD + d) * DHEAD + e4];
        }
    }
    if (tid < 64) {
        float s = 0.0f;
#pragma unroll
        for (int p = 0; p < NSPLIT; p++)
            s += ksump[((size_t)bh * NSPLIT + p) * DHEAD + tid];
        ksum[tid] = s;
    }
    __syncthreads();
    if (tid < 64) {
        float s = 0.0f;
#pragma unroll
        for (int d = 0; d < 64; d++) s += qst[d][tid] * ksum[d];
        dinv[tid] = 1.0f / s;
    }
    __syncthreads();

    int ty = tid >> 4, tx = tid & 15;
    float acc[4][4];
#pragma unroll
    for (int i = 0; i < 4; i++)
#pragma unroll
        for (int j = 0; j < 4; j++) acc[i][j] = 0.0f;

#pragma unroll 8
    for (int d = 0; d < 64; d++) {
        float af[4], bf[4];
#pragma unroll
        for (int i = 0; i < 4; i++) af[i] = qst[d][ty + 16 * i];
#pragma unroll
        for (int j = 0; j < 4; j++) bf[j] = cs[d][tx + 16 * j];
#pragma unroll
        for (int i = 0; i < 4; i++)
#pragma unroll
            for (int j = 0; j < 4; j++) acc[i][j] += af[i] * bf[j];
    }

#pragma unroll
    for (int i = 0; i < 4; i++) {
        int r = ty + 16 * i;
        float di = dinv[r];
#pragma unroll
        for (int j = 0; j < 4; j++) {
            int e = tx + 16 * j;
            float val = acc[i][j] * di + qst[e][r];
            size_t idx = (size_t)(t0 + r) * DIMQ + h * DHEAD + e;
            __nv_bfloat16 hi = __float2bfloat16(val);
            outh[idx] = hi;
            outl[idx] = __float2bfloat16(val - __bfloat162float(hi));
        }
    }
}

// ---------------------------------------------------------------------------
extern "C" void kernel_launch(void* const* d_in, const int* in_sizes, int n_in,
                              void* d_out, int out_size)
{
    const float* x  = (const float*)d_in[0];
    const float* Wq = (const float*)d_in[1];
    const float* bq = (const float*)d_in[2];
    const float* Wk = (const float*)d_in[3];
    const float* bk = (const float*)d_in[4];
    const float* Wv = (const float*)d_in[5];
    const float* bv = (const float*)d_in[6];
    const float* Wp = (const float*)d_in[7];
    const float* bp = (const float*)d_in[8];
    float* out = (float*)d_out;

    float *q, *ctx, *ctxp, *ksump;
    __nv_bfloat16 *kh, *kl, *vh, *vl, *xh, *xl, *atth, *attl, *wh, *wl;
    cudaGetSymbolAddress((void**)&q, g_q);
    cudaGetSymbolAddress((void**)&kh, g_kh);
    cudaGetSymbolAddress((void**)&kl, g_kl);
    cudaGetSymbolAddress((void**)&vh, g_vh);
    cudaGetSymbolAddress((void**)&vl, g_vl);
    cudaGetSymbolAddress((void**)&ctx, g_ctx);
    cudaGetSymbolAddress((void**)&ctxp, g_ctxp);
    cudaGetSymbolAddress((void**)&ksump, g_ksump);
    cudaGetSymbolAddress((void**)&xh, g_xh);
    cudaGetSymbolAddress((void**)&xl, g_xl);
    cudaGetSymbolAddress((void**)&atth, g_atth);
    cudaGetSymbolAddress((void**)&attl, g_attl);
    cudaGetSymbolAddress((void**)&wh, g_wh);
    cudaGetSymbolAddress((void**)&wl, g_wl);

    cudaFuncSetAttribute(gemm_bf16x3_kernel,
                         cudaFuncAttributeMaxDynamicSharedMemorySize, GEMM_SMEM);
    cudaFuncSetAttribute(ctx_mma_kernel,
                         cudaFuncAttributeMaxDynamicSharedMemorySize, CTX_SMEM);

    const int WN = DIMQ * DIMQ;

    hilo_kernel<<<(NT * DIMQ) / (256 * 4), 256>>>(x, xh, xl);
    WPtrs wp; wp.w[0] = Wq; wp.w[1] = Wk; wp.w[2] = Wv; wp.w[3] = Wp;
    hilo_w4_kernel<<<dim3(WN / (256 * 4), 4), 256>>>(wp, wh, wl);

    // merged QKV GEMM: q fp32+softmax; k bf16 hi/lo+softmax; v bf16 hi/lo
    gemm_bf16x3_kernel<<<dim3(3 * DIMQ / GBN, NT / GBM), 256, GEMM_SMEM>>>(
        xh, xl, wh, wl, bq, bk, bv, q, kh, kl, vh, vl, 0b011);

    ctx_mma_kernel<<<dim3(NB * HEADS, NSPLIT), 128, CTX_SMEM>>>(
        kh, kl, vh, vl, ctxp, ksump);
    ctx_reduce_kernel<<<NB * HEADS, 256>>>(ctxp, ctx);

    attn_out_kernel<<<dim3(HEADS, NT / 64), 256>>>(q, ctx, ksump, atth, attl);

    // output projection (widx==0 path -> fp32 out, no softmax)
    gemm_bf16x3_kernel<<<dim3(DIMQ / GBN, NT / GBM), 256, GEMM_SMEM>>>(
        atth, attl, wh + 3 * WN, wl + 3 * WN, bp, bp, bp, out,
        kh, kl, vh, vl, 0);
}

// round 14
// speedup vs baseline: 1.2940x; 1.0309x over previous
#include <cuda_runtime.h>
#include <cuda_bf16.h>
#include <cstdint>
#include <math.h>

// Problem constants
#define NT    16384      // B*T tokens
#define DIMQ  512
#define HEADS 8
#define DHEAD 64
#define TLEN  4096       // T per batch
#define NB    4          // batch
#define NSPLIT 32        // T-splits for ctx partials (128 tokens each)

// ---------------------------------------------------------------------------
// Scratch (device globals — no allocation allowed)
// ---------------------------------------------------------------------------
__device__ __nv_bfloat16  g_qh[NT * DIMQ];
__device__ __nv_bfloat16  g_ql[NT * DIMQ];
__device__ __nv_bfloat16  g_kh[NT * DIMQ];
__device__ __nv_bfloat16  g_kl[NT * DIMQ];
__device__ __nv_bfloat16  g_vh[NT * DIMQ];
__device__ __nv_bfloat16  g_vl[NT * DIMQ];
__device__ __nv_bfloat16  g_xh[NT * DIMQ];
__device__ __nv_bfloat16  g_xl[NT * DIMQ];
__device__ __nv_bfloat16  g_atth[NT * DIMQ];
__device__ __nv_bfloat16  g_attl[NT * DIMQ];
__device__ __nv_bfloat16  g_wh[4 * DIMQ * DIMQ];
__device__ __nv_bfloat16  g_wl[4 * DIMQ * DIMQ];
__device__ float          g_ctxp[NB * HEADS * NSPLIT * DHEAD * DHEAD];
__device__ float          g_ksump[NB * HEADS * NSPLIT * DHEAD];
__device__ __nv_bfloat16  g_cth[NB * HEADS * DHEAD * DHEAD];  // ctx^T hi
__device__ __nv_bfloat16  g_ctl[NB * HEADS * DHEAD * DHEAD];  // ctx^T lo
__device__ float          g_ksum[NB * HEADS * DHEAD];

#define SWZ128(x) ((x) ^ (((x) >> 3) & 0x70))

// ---------------------------------------------------------------------------
// warp-MMA helpers
// ---------------------------------------------------------------------------
__device__ __forceinline__ uint32_t smem_u32(const void* p) {
    uint32_t a;
    asm("{ .reg .u64 t; cvta.to.shared.u64 t, %1; cvt.u32.u64 %0, t; }"
        : "=r"(a) : "l"(p));
    return a;
}

__device__ __forceinline__ void cp_async16(uint32_t saddr, const void* gaddr) {
    asm volatile("cp.async.cg.shared.global [%0], [%1], 16;"
                 :: "r"(saddr), "l"(gaddr) : "memory");
}
#define CP_COMMIT() asm volatile("cp.async.commit_group;" ::: "memory")
#define CP_WAIT2()  asm volatile("cp.async.wait_group 2;" ::: "memory")
#define CP_WAIT1()  asm volatile("cp.async.wait_group 1;" ::: "memory")
#define CP_WAIT0()  asm volatile("cp.async.wait_group 0;" ::: "memory")

__device__ __forceinline__ void ldsm4(uint32_t* r, uint32_t addr) {
    asm volatile("ldmatrix.sync.aligned.m8n8.x4.shared.b16 {%0,%1,%2,%3}, [%4];"
                 : "=r"(r[0]), "=r"(r[1]), "=r"(r[2]), "=r"(r[3]) : "r"(addr));
}
__device__ __forceinline__ void ldsm4t(uint32_t* r, uint32_t addr) {
    asm volatile("ldmatrix.sync.aligned.m8n8.x4.trans.shared.b16 {%0,%1,%2,%3}, [%4];"
                 : "=r"(r[0]), "=r"(r[1]), "=r"(r[2]), "=r"(r[3]) : "r"(addr));
}

__device__ __forceinline__ void mma_bf16(float* c, const uint32_t* a,
                                         const uint32_t* b) {
    asm volatile(
        "mma.sync.aligned.m16n8k16.row.col.f32.bf16.bf16.f32 "
        "{%0,%1,%2,%3}, {%4,%5,%6,%7}, {%8,%9}, {%0,%1,%2,%3};"
        : "+f"(c[0]), "+f"(c[1]), "+f"(c[2]), "+f"(c[3])
        : "r"(a[0]), "r"(a[1]), "r"(a[2]), "r"(a[3]), "r"(b[0]), "r"(b[1]));
}

__device__ __forceinline__ float lds_bf16(uint32_t a) {
    uint32_t v;
    asm volatile("ld.shared.u16 %0, [%1];" : "=r"(v) : "r"(a));
    __nv_bfloat16_raw r; r.x = (unsigned short)v;
    return __bfloat162float(__nv_bfloat16(r));
}

__device__ __forceinline__ float2 bf2_to_f2(uint32_t u) {
    __nv_bfloat162 p = *reinterpret_cast<__nv_bfloat162*>(&u);
    return __bfloat1622float2(p);
}

// ---------------------------------------------------------------------------
// fp32 -> bf16 hi/lo split conversion
// ---------------------------------------------------------------------------
__global__ __launch_bounds__(256) void hilo_kernel(
    const float* __restrict__ in, __nv_bfloat16* __restrict__ hi,
    __nv_bfloat16* __restrict__ lo)
{
    size_t i = ((size_t)blockIdx.x * 256 + threadIdx.x) * 4;
    float4 v = *(const float4*)(in + i);
    __nv_bfloat16 h0 = __float2bfloat16(v.x);
    __nv_bfloat16 h1 = __float2bfloat16(v.y);
    __nv_bfloat16 h2 = __float2bfloat16(v.z);
    __nv_bfloat16 h3 = __float2bfloat16(v.w);
    __nv_bfloat16 l0 = __float2bfloat16(v.x - __bfloat162float(h0));
    __nv_bfloat16 l1 = __float2bfloat16(v.y - __bfloat162float(h1));
    __nv_bfloat16 l2 = __float2bfloat16(v.z - __bfloat162float(h2));
    __nv_bfloat16 l3 = __float2bfloat16(v.w - __bfloat162float(h3));
    *(__nv_bfloat162*)(hi + i)     = __nv_bfloat162(h0, h1);
    *(__nv_bfloat162*)(hi + i + 2) = __nv_bfloat162(h2, h3);
    *(__nv_bfloat162*)(lo + i)     = __nv_bfloat162(l0, l1);
    *(__nv_bfloat162*)(lo + i + 2) = __nv_bfloat162(l2, l3);
}

struct WPtrs { const float* w[4]; };
__global__ __launch_bounds__(256) void hilo_w4_kernel(
    WPtrs p, __nv_bfloat16* __restrict__ hi, __nv_bfloat16* __restrict__ lo)
{
    const int WN = DIMQ * DIMQ;
    const float* in = p.w[blockIdx.y];
    size_t off = (size_t)blockIdx.y * WN;
    size_t i = ((size_t)blockIdx.x * 256 + threadIdx.x) * 4;
    float4 v = *(const float4*)(in + i);
    __nv_bfloat16 h0 = __float2bfloat16(v.x);
    __nv_bfloat16 h1 = __float2bfloat16(v.y);
    __nv_bfloat16 h2 = __float2bfloat16(v.z);
    __nv_bfloat16 h3 = __float2bfloat16(v.w);
    __nv_bfloat16 l0 = __float2bfloat16(v.x - __bfloat162float(h0));
    __nv_bfloat16 l1 = __float2bfloat16(v.y - __bfloat162float(h1));
    __nv_bfloat16 l2 = __float2bfloat16(v.z - __bfloat162float(h2));
    __nv_bfloat16 l3 = __float2bfloat16(v.w - __bfloat162float(h3));
    *(__nv_bfloat162*)(hi + off + i)     = __nv_bfloat162(h0, h1);
    *(__nv_bfloat162*)(hi + off + i + 2) = __nv_bfloat162(h2, h3);
    *(__nv_bfloat162*)(lo + off + i)     = __nv_bfloat162(l0, l1);
    *(__nv_bfloat162*)(lo + off + i + 2) = __nv_bfloat162(l2, l3);
}

// ---------------------------------------------------------------------------
// bf16x3 GEMM with fused per-head softmax epilogue.
// Cf != nullptr -> fp32 output (final projection). Otherwise bf16 hi/lo
// to op.h[widx]/op.l[widx] (q/k/v).
// ---------------------------------------------------------------------------
#define GBM 128
#define GBN 128
#define GKS 64
#define GNSL (DIMQ / GKS)
#define TILE_BYTES (128 * 128)
#define STAGE_BYTES (4 * TILE_BYTES)
#define GEMM_SMEM (3 * STAGE_BYTES)

struct OutPtrs { __nv_bfloat16 *h[3]; __nv_bfloat16 *l[3]; };

__global__ __launch_bounds__(256) void gemm_bf16x3_kernel(
    const __nv_bfloat16* __restrict__ Ah, const __nv_bfloat16* __restrict__ Al,
    const __nv_bfloat16* __restrict__ Wh, const __nv_bfloat16* __restrict__ Wl,
    const float* __restrict__ b0, const float* __restrict__ b1,
    const float* __restrict__ b2,
    float* __restrict__ Cf, OutPtrs op, int sm_mask)
{
    extern __shared__ __align__(1024) char sm[];
    uint32_t smb = smem_u32(sm);

    const int tid  = threadIdx.x;
    const int wid  = tid >> 5;
    const int lane = tid & 31;
    const int m0 = blockIdx.y * GBM;
    const int n0 = blockIdx.x * GBN;

    const int widx = n0 >> 9;
    const int col0 = n0 & 511;
    const float* bias = (widx == 0) ? b0 : (widx == 1) ? b1 : b2;
    const bool do_sm  = (sm_mask >> widx) & 1;

    const int warp_m = wid & 3;
    const int warp_n = wid >> 2;
    const int mbase = warp_m * 32;
    const int nbase = warp_n * 64;

    const int lr = lane & 7;
    const int g  = lane >> 3;
    const uint32_t aoff = (uint32_t)(((g & 1) * 8 + lr) * 128 + (g >> 1) * 16);
    const uint32_t boff = (uint32_t)(((g >> 1) * 8 + lr) * 128 + (g & 1) * 16);

    const __nv_bfloat16* srcs[4] = {Ah, Al, Wh, Wl};

    float acc[2][8][4];
#pragma unroll
    for (int i = 0; i < 2; i++)
#pragma unroll
        for (int j = 0; j < 8; j++)
#pragma unroll
            for (int c = 0; c < 4; c++) acc[i][j][c] = 0.0f;

    auto load_stage = [&](int s) {
        uint32_t stb = smb + (uint32_t)(s % 3) * STAGE_BYTES;
        int k0 = s * GKS;
#pragma unroll
        for (int t = 0; t < 4; t++) {
            const __nv_bfloat16* src = srcs[t];
            int r0 = (t < 2) ? m0 : n0;
            uint32_t tb = stb + (uint32_t)t * TILE_BYTES;
#pragma unroll
            for (int j = 0; j < 4; j++) {
                int il  = tid + j * 256;
                int row = il >> 3;
                int ch  = il & 7;
                uint32_t sa = tb + SWZ128((uint32_t)(row * 128 + ch * 16));
                const void* ga = src + (size_t)(r0 + row) * DIMQ + k0 + ch * 8;
                cp_async16(sa, ga);
            }
        }
    };

    load_stage(0); CP_COMMIT();
    load_stage(1); CP_COMMIT();

    for (int s = 0; s < GNSL; s++) {
        if (s + 2 < GNSL) load_stage(s + 2);
        CP_COMMIT();
        CP_WAIT2();
        __syncthreads();

        uint32_t stb  = smb + (uint32_t)(s % 3) * STAGE_BYTES;
        uint32_t ah_b = stb;
        uint32_t wh_b = stb + 2 * TILE_BYTES;

#pragma unroll
        for (int ks = 0; ks < 4; ks++) {
            uint32_t ksb = (uint32_t)(ks * 32);
            uint32_t aH[2][4], aL[2][4], bH[4][4], bL[4][4];
#pragma unroll
            for (int am = 0; am < 2; am++) {
                uint32_t ad = ah_b + (uint32_t)((mbase + am * 16) * 128)
                            + SWZ128(aoff + ksb);
                ldsm4(aH[am], ad);
                ldsm4(aL[am], ad + TILE_BYTES);
            }
#pragma unroll
            for (int nq = 0; nq < 4; nq++) {
                uint32_t bd = wh_b + (uint32_t)((nbase + nq * 16) * 128)
                            + SWZ128(boff + ksb);
                ldsm4(bH[nq], bd);
                ldsm4(bL[nq], bd + TILE_BYTES);
            }
#pragma unroll
            for (int am = 0; am < 2; am++)
#pragma unroll
                for (int na = 0; na < 8; na++) {
                    const uint32_t* bh = &bH[na >> 1][(na & 1) * 2];
                    const uint32_t* bl = &bL[na >> 1][(na & 1) * 2];
                    mma_bf16(acc[am][na], aH[am], bh);
                    mma_bf16(acc[am][na], aH[am], bl);
                    mma_bf16(acc[am][na], aL[am], bh);
                }
        }
        __syncthreads();
    }

    const int row_in = lane >> 2;
    const int col_in = (lane & 3) * 2;

    __nv_bfloat16* Oh = op.h[widx];
    __nv_bfloat16* Ol = op.l[widx];

    float bb[16];
#pragma unroll
    for (int na = 0; na < 8; na++) {
        float2 b = *(const float2*)&bias[col0 + nbase + na * 8 + col_in];
        bb[na * 2] = b.x; bb[na * 2 + 1] = b.y;
    }

#pragma unroll
    for (int am = 0; am < 2; am++) {
#pragma unroll
        for (int sub = 0; sub < 2; sub++) {
            float v[16];
#pragma unroll
            for (int na = 0; na < 8; na++) {
                v[na * 2]     = acc[am][na][sub * 2]     + bb[na * 2];
                v[na * 2 + 1] = acc[am][na][sub * 2 + 1] + bb[na * 2 + 1];
            }
            if (do_sm) {
                float m = v[0];
#pragma unroll
                for (int i = 1; i < 16; i++) m = fmaxf(m, v[i]);
                m = fmaxf(m, __shfl_xor_sync(0xffffffffu, m, 1));
                m = fmaxf(m, __shfl_xor_sync(0xffffffffu, m, 2));
                float ssum = 0.0f;
#pragma unroll
                for (int i = 0; i < 16; i++) { v[i] = __expf(v[i] - m); ssum += v[i]; }
                ssum += __shfl_xor_sync(0xffffffffu, ssum, 1);
                ssum += __shfl_xor_sync(0xffffffffu, ssum, 2);
                float inv = 1.0f / ssum;
#pragma unroll
                for (int i = 0; i < 16; i++) v[i] *= inv;
            }
            int r = m0 + mbase + am * 16 + sub * 8 + row_in;
            if (Cf) {
#pragma unroll
                for (int na = 0; na < 8; na++) {
                    int c = col0 + nbase + na * 8 + col_in;
                    *(float2*)&Cf[(size_t)r * DIMQ + c] =
                        make_float2(v[na * 2], v[na * 2 + 1]);
                }
            } else {
#pragma unroll
                for (int na = 0; na < 8; na++) {
                    int c = col0 + nbase + na * 8 + col_in;
                    __nv_bfloat16 h0 = __float2bfloat16(v[na * 2]);
                    __nv_bfloat16 h1 = __float2bfloat16(v[na * 2 + 1]);
                    __nv_bfloat16 l0 = __float2bfloat16(v[na * 2]     - __bfloat162float(h0));
                    __nv_bfloat16 l1 = __float2bfloat16(v[na * 2 + 1] - __bfloat162float(h1));
                    *(__nv_bfloat162*)&Oh[(size_t)r * DIMQ + c] = __nv_bfloat162(h0, h1);
                    *(__nv_bfloat162*)&Ol[(size_t)r * DIMQ + c] = __nv_bfloat162(l0, l1);
                }
            }
        }
    }
}

// ---------------------------------------------------------------------------
// ctx partials via tensor cores. grid (32, NSPLIT=32), 128 threads.
// ---------------------------------------------------------------------------
#define CCH 64
#define CTILE 8192
#define CSTAGE (4 * CTILE)
#define CTX_SMEM (2 * CSTAGE)

__global__ __launch_bounds__(128) void ctx_mma_kernel(
    const __nv_bfloat16* __restrict__ Kh, const __nv_bfloat16* __restrict__ Kl,
    const __nv_bfloat16* __restrict__ Vh, const __nv_bfloat16* __restrict__ Vl,
    float* __restrict__ ctxp, float* __restrict__ ksump)
{
    extern __shared__ __align__(1024) char sm[];
    uint32_t smb = smem_u32(sm);

    const int bh = blockIdx.x;
    const int s  = blockIdx.y;
    const int b = bh >> 3, h = bh & 7;
    const int tid = threadIdx.x;
    const int wid = tid >> 5, lane = tid & 31;

    const size_t tok0 = (size_t)b * TLEN + s * (TLEN / NSPLIT);
    const __nv_bfloat16* srcs[4] = {Kh, Kl, Vh, Vl};

    const int arow = (lane & 7) + 8 * ((lane >> 4) & 1);
    const int acolX = wid * 32 + 16 * ((lane >> 3) & 1);
    const int brow = (lane & 7) + 8 * ((lane >> 3) & 1);
    const int bcolX = 16 * ((lane >> 4) & 1);

    auto load_chunk = [&](int c, int buf) {
        uint32_t stb = smb + (uint32_t)buf * CSTAGE;
#pragma unroll
        for (int i = 0; i < 16; i++) {
            int idx  = tid + i * 128;
            int tile = idx >> 9;
            int rem  = idx & 511;
            int row  = rem >> 3;
            int ch   = rem & 7;
            uint32_t sa = stb + (uint32_t)tile * CTILE
                        + SWZ128((uint32_t)(row * 128 + ch * 16));
            const void* ga = srcs[tile]
                + (tok0 + c * CCH + row) * DIMQ + h * DHEAD + ch * 8;
            cp_async16(sa, ga);
        }
    };

    float acc[8][4];
#pragma unroll
    for (int j = 0; j < 8; j++)
#pragma unroll
        for (int c = 0; c < 4; c++) acc[j][c] = 0.0f;
    float ksacc = 0.0f;

    load_chunk(0, 0); CP_COMMIT();

    const int NCH = (TLEN / NSPLIT) / CCH;  // 2
    for (int c = 0; c < NCH; c++) {
        if (c + 1 < NCH) load_chunk(c + 1, (c + 1) & 1);
        CP_COMMIT();
        CP_WAIT1();
        __syncthreads();

        uint32_t st = smb + (uint32_t)(c & 1) * CSTAGE;
#pragma unroll
        for (int kk = 0; kk < 4; kk++) {
            int t0 = kk * 16;
            uint32_t aH[4], aL[4], vH[4][4], vL[4][4];
            uint32_t ad = st + SWZ128((uint32_t)((t0 + arow) * 128 + acolX));
            ldsm4t(aH, ad);
            ldsm4t(aL, ad + CTILE);
#pragma unroll
            for (int nb2 = 0; nb2 < 4; nb2++) {
                uint32_t bd = st + 2 * CTILE
                    + SWZ128((uint32_t)((t0 + brow) * 128 + nb2 * 32 + bcolX));
                ldsm4t(vH[nb2], bd);
                ldsm4t(vL[nb2], bd + CTILE);
            }
#pragma unroll
            for (int nb = 0; nb < 8; nb++) {
                const uint32_t* bh_ = &vH[nb >> 1][(nb & 1) * 2];
                const uint32_t* bl_ = &vL[nb >> 1][(nb & 1) * 2];
                mma_bf16(acc[nb], aH, bh_);
                mma_bf16(acc[nb], aH, bl_);
                mma_bf16(acc[nb], aL, bh_);
            }
        }
        if (tid < 64) {
#pragma unroll 8
            for (int t = 0; t < CCH; t++) {
                uint32_t off = SWZ128((uint32_t)(t * 128 + tid * 2));
                ksacc += lds_bf16(st + off) + lds_bf16(st + CTILE + off);
            }
        }
        __syncthreads();
    }

    size_t obase = ((size_t)bh * NSPLIT + s) * (DHEAD * DHEAD);
    int r1 = wid * 16 + (lane >> 2);
    int ec = (lane & 3) * 2;
#pragma unroll
    for (int nb = 0; nb < 8; nb++) {
        int e = nb * 8 + ec;
        *(float2*)&ctxp[obase + (size_t)r1 * DHEAD + e] =
            make_float2(acc[nb][0], acc[nb][1]);
        *(float2*)&ctxp[obase + (size_t)(r1 + 8) * DHEAD + e] =
            make_float2(acc[nb][2], acc[nb][3]);
    }
    if (tid < 64)
        ksump[((size_t)bh * NSPLIT + s) * DHEAD + tid] = ksacc;
}

// ---------------------------------------------------------------------------
// Reduce ctx partials -> ctx^T bf16 hi/lo; reduce ksum partials -> fp32.
// ---------------------------------------------------------------------------
__global__ __launch_bounds__(256) void ctx_reduce_kernel(
    const float* __restrict__ ctxp, const float* __restrict__ ksump,
    __nv_bfloat16* __restrict__ cth, __nv_bfloat16* __restrict__ ctl,
    float* __restrict__ ksum)
{
    int bh = blockIdx.x;
    for (int idx = threadIdx.x; idx < DHEAD * DHEAD; idx += blockDim.x) {
        float s = 0.0f;
#pragma unroll
        for (int p = 0; p < NSPLIT; p++)
            s += ctxp[(size_t)(bh * NSPLIT + p) * DHEAD * DHEAD + idx];
        int d = idx >> 6, e = idx & 63;
        __nv_bfloat16 h = __float2bfloat16(s);
        size_t o = (size_t)bh * DHEAD * DHEAD + (size_t)e * DHEAD + d;
        cth[o] = h;
        ctl[o] = __float2bfloat16(s - __bfloat162float(h));
    }
    if (threadIdx.x < DHEAD) {
        float s = 0.0f;
#pragma unroll
        for (int p = 0; p < NSPLIT; p++)
            s += ksump[(size_t)(bh * NSPLIT + p) * DHEAD + threadIdx.x];
        ksum[bh * DHEAD + threadIdx.x] = s;
    }
}

// ---------------------------------------------------------------------------
// Apply attention via tensor cores:
// att[t][e] = (sum_d q[t][d]*ctx[d][e]) * Dinv[t] + q[t][e], bf16x3.
// grid (bh=32, 4096/128=32), 128 threads (4 warps x 32 token rows).
// ---------------------------------------------------------------------------
#define AT_QH 0
#define AT_QL 16384
#define AT_CH 32768
#define AT_CL 40960
#define AT_KS 49152                    // float[64]
#define AT_DI 49408                    // float[128]
#define AT_SMEM 49920

__global__ __launch_bounds__(128) void attn_mma_kernel(
    const __nv_bfloat16* __restrict__ Qh, const __nv_bfloat16* __restrict__ Ql,
    const __nv_bfloat16* __restrict__ cth, const __nv_bfloat16* __restrict__ ctl,
    const float* __restrict__ ksum,
    __nv_bfloat16* __restrict__ outh, __nv_bfloat16* __restrict__ outl)
{
    extern __shared__ __align__(1024) char sm[];
    uint32_t smb = smem_u32(sm);
    float* ksum_s = (float*)(sm + AT_KS);
    float* dinv_s = (float*)(sm + AT_DI);

    const int bh = blockIdx.x;
    const int b = bh >> 3, h = bh & 7;
    const size_t tok0 = (size_t)b * TLEN + blockIdx.y * 128;
    const int tid = threadIdx.x;
    const int wid = tid >> 5, lane = tid & 31;

    // ---- load tiles: qh/ql [128 x 64], ctxT hi/lo [64 x 64] ----
#pragma unroll
    for (int i = 0; i < 8; i++) {   // q tiles: 1024 chunks each
        int idx = tid + i * 128;
        int row = idx >> 3, ch = idx & 7;
        uint32_t so = SWZ128((uint32_t)(row * 128 + ch * 16));
        const size_t go = (tok0 + row) * DIMQ + h * DHEAD + ch * 8;
        cp_async16(smb + AT_QH + so, Qh + go);
        cp_async16(smb + AT_QL + so, Ql + go);
    }
#pragma unroll
    for (int i = 0; i < 4; i++) {   // ctxT tiles: 512 chunks each
        int idx = tid + i * 128;
        int row = idx >> 3, ch = idx & 7;
        uint32_t so = SWZ128((uint32_t)(row * 128 + ch * 16));
        const size_t go = (size_t)bh * DHEAD * DHEAD + (size_t)row * DHEAD + ch * 8;
        cp_async16(smb + AT_CH + so, cth + go);
        cp_async16(smb + AT_CL + so, ctl + go);
    }
    if (tid < 64) ksum_s[tid] = ksum[bh * DHEAD + tid];
    CP_COMMIT();
    CP_WAIT0();
    __syncthreads();

    // ---- Dinv per token (thread = token) ----
    {
        float dot = 0.0f;
#pragma unroll
        for (int ch = 0; ch < 8; ch++) {
            uint32_t so = SWZ128((uint32_t)(tid * 128 + ch * 16));
            uint4 wh4 = *(const uint4*)(sm + AT_QH + so);
            uint4 wl4 = *(const uint4*)(sm + AT_QL + so);
            const uint32_t wh[4] = {wh4.x, wh4.y, wh4.z, wh4.w};
            const uint32_t wl[4] = {wl4.x, wl4.y, wl4.z, wl4.w};
#pragma unroll
            for (int j = 0; j < 4; j++) {
                float2 fh = bf2_to_f2(wh[j]);
                float2 fl = bf2_to_f2(wl[j]);
                int d = ch * 8 + j * 2;
                dot += (fh.x + fl.x) * ksum_s[d];
                dot += (fh.y + fl.y) * ksum_s[d + 1];
            }
        }
        dinv_s[tid] = 1.0f / dot;
    }
    __syncthreads();

    // ---- MMA: [128 x 64] = q[128 x 64] @ ctxT^T ----
    const int lr = lane & 7;
    const int g  = lane >> 3;
    const uint32_t aoff = (uint32_t)(((g & 1) * 8 + lr) * 128 + (g >> 1) * 16);
    const uint32_t boff = (uint32_t)(((g >> 1) * 8 + lr) * 128 + (g & 1) * 16);
    const int mbase = wid * 32;

    float acc[2][8][4];
#pragma unroll
    for (int i = 0; i < 2; i++)
#pragma unroll
        for (int j = 0; j < 8; j++)
#pragma unroll
            for (int c = 0; c < 4; c++) acc[i][j][c] = 0.0f;

#pragma unroll
    for (int ks = 0; ks < 4; ks++) {
        uint32_t ksb = (uint32_t)(ks * 32);
        uint32_t aH[2][4], aL[2][4], bH[4][4], bL[4][4];
#pragma unroll
        for (int am = 0; am < 2; am++) {
            uint32_t ad = smb + AT_QH + (uint32_t)((mbase + am * 16) * 128)
                        + SWZ128(aoff + ksb);
            ldsm4(aH[am], ad);
            ldsm4(aL[am], ad + (AT_QL - AT_QH));
        }
#pragma unroll
        for (int nq = 0; nq < 4; nq++) {
            uint32_t bd = smb + AT_CH + (uint32_t)((nq * 16) * 128)
                        + SWZ128(boff + ksb);
            ldsm4(bH[nq], bd);
            ldsm4(bL[nq], bd + (AT_CL - AT_CH));
        }
#pragma unroll
        for (int am = 0; am < 2; am++)
#pragma unroll
            for (int na = 0; na < 8; na++) {
                const uint32_t* bh_ = &bH[na >> 1][(na & 1) * 2];
                const uint32_t* bl_ = &bL[na >> 1][(na & 1) * 2];
                mma_bf16(acc[am][na], aH[am], bh_);
                mma_bf16(acc[am][na], aH[am], bl_);
                mma_bf16(acc[am][na], aL[am], bh_);
            }
    }

    // ---- epilogue: *Dinv + q, write bf16 hi/lo ----
    const int row_in = lane >> 2;
    const int col_in = (lane & 3) * 2;
#pragma unroll
    for (int am = 0; am < 2; am++) {
#pragma unroll
        for (int sub = 0; sub < 2; sub++) {
            int r = mbase + am * 16 + sub * 8 + row_in;
            float di = dinv_s[r];
#pragma unroll
            for (int na = 0; na < 8; na++) {
                int c = na * 8 + col_in;
                uint32_t so = SWZ128((uint32_t)(r * 128 + c * 2));
                float2 qh2 = bf2_to_f2(*(const uint32_t*)(sm + AT_QH + so));
                float2 ql2 = bf2_to_f2(*(const uint32_t*)(sm + AT_QL + so));
                float v0 = acc[am][na][sub * 2]     * di + qh2.x + ql2.x;
                float v1 = acc[am][na][sub * 2 + 1] * di + qh2.y + ql2.y;
                __nv_bfloat16 h0 = __float2bfloat16(v0);
                __nv_bfloat16 h1 = __float2bfloat16(v1);
                __nv_bfloat16 l0 = __float2bfloat16(v0 - __bfloat162float(h0));
                __nv_bfloat16 l1 = __float2bfloat16(v1 - __bfloat162float(h1));
                size_t idx = (tok0 + r) * DIMQ + h * DHEAD + c;
                *(__nv_bfloat162*)&outh[idx] = __nv_bfloat162(h0, h1);
                *(__nv_bfloat162*)&outl[idx] = __nv_bfloat162(l0, l1);
            }
        }
    }
}

// ---------------------------------------------------------------------------
extern "C" void kernel_launch(void* const* d_in, const int* in_sizes, int n_in,
                              void* d_out, int out_size)
{
    const float* x  = (const float*)d_in[0];
    const float* Wq = (const float*)d_in[1];
    const float* bq = (const float*)d_in[2];
    const float* Wk = (const float*)d_in[3];
    const float* bk = (const float*)d_in[4];
    const float* Wv = (const float*)d_in[5];
    const float* bv = (const float*)d_in[6];
    const float* Wp = (const float*)d_in[7];
    const float* bp = (const float*)d_in[8];
    float* out = (float*)d_out;

    float *ctxp, *ksump, *ksum;
    __nv_bfloat16 *qh, *ql, *kh, *kl, *vh, *vl, *xh, *xl, *atth, *attl, *wh, *wl, *cth, *ctl;
    cudaGetSymbolAddress((void**)&qh, g_qh);
    cudaGetSymbolAddress((void**)&ql, g_ql);
    cudaGetSymbolAddress((void**)&kh, g_kh);
    cudaGetSymbolAddress((void**)&kl, g_kl);
    cudaGetSymbolAddress((void**)&vh, g_vh);
    cudaGetSymbolAddress((void**)&vl, g_vl);
    cudaGetSymbolAddress((void**)&ctxp, g_ctxp);
    cudaGetSymbolAddress((void**)&ksump, g_ksump);
    cudaGetSymbolAddress((void**)&ksum, g_ksum);
    cudaGetSymbolAddress((void**)&cth, g_cth);
    cudaGetSymbolAddress((void**)&ctl, g_ctl);
    cudaGetSymbolAddress((void**)&xh, g_xh);
    cudaGetSymbolAddress((void**)&xl, g_xl);
    cudaGetSymbolAddress((void**)&atth, g_atth);
    cudaGetSymbolAddress((void**)&attl, g_attl);
    cudaGetSymbolAddress((void**)&wh, g_wh);
    cudaGetSymbolAddress((void**)&wl, g_wl);

    cudaFuncSetAttribute(gemm_bf16x3_kernel,
                         cudaFuncAttributeMaxDynamicSharedMemorySize, GEMM_SMEM);
    cudaFuncSetAttribute(ctx_mma_kernel,
                         cudaFuncAttributeMaxDynamicSharedMemorySize, CTX_SMEM);
    cudaFuncSetAttribute(attn_mma_kernel,
                         cudaFuncAttributeMaxDynamicSharedMemorySize, AT_SMEM);

    const int WN = DIMQ * DIMQ;

    hilo_kernel<<<(NT * DIMQ) / (256 * 4), 256>>>(x, xh, xl);
    WPtrs wp; wp.w[0] = Wq; wp.w[1] = Wk; wp.w[2] = Wv; wp.w[3] = Wp;
    hilo_w4_kernel<<<dim3(WN / (256 * 4), 4), 256>>>(wp, wh, wl);

    // merged QKV GEMM: all outputs bf16 hi/lo; softmax on q,k
    OutPtrs opqkv;
    opqkv.h[0] = qh; opqkv.h[1] = kh; opqkv.h[2] = vh;
    opqkv.l[0] = ql; opqkv.l[1] = kl; opqkv.l[2] = vl;
    gemm_bf16x3_kernel<<<dim3(3 * DIMQ / GBN, NT / GBM), 256, GEMM_SMEM>>>(
        xh, xl, wh, wl, bq, bk, bv, nullptr, opqkv, 0b011);

    ctx_mma_kernel<<<dim3(NB * HEADS, NSPLIT), 128, CTX_SMEM>>>(
        kh, kl, vh, vl, ctxp, ksump);
    ctx_reduce_kernel<<<NB * HEADS, 256>>>(ctxp, ksump, cth, ctl, ksum);

    attn_mma_kernel<<<dim3(NB * HEADS, TLEN / 128), 128, AT_SMEM>>>(
        qh, ql, cth, ctl, ksum, atth, attl);

    // output projection -> fp32 out
    OutPtrs opf = {};
    gemm_bf16x3_kernel<<<dim3(DIMQ / GBN, NT / GBM), 256, GEMM_SMEM>>>(
        atth, attl, wh + 3 * WN, wl + 3 * WN, bp, bp, bp, out, opf, 0);
}